// round 1
// baseline (speedup 1.0000x reference)
#include <cuda_runtime.h>
#include <math.h>

// ---------------------------------------------------------------------------
// Problem constants
//   x_in [4,16,32,32,256], qkv_w [256,768], proj_w [256,256], proj_b [256]
//   rpb_table [343,8], fc_w [27,24], fc_b [27], dep_w [256,27,3,3,3],
//   dep_b [256], alpha, beta (scalars)
//   out [4,16,32,32,256] float32
// ---------------------------------------------------------------------------
#define LSP 16384   // 16*32*32 spatial per batch

// Scratch (device globals: allocation is forbidden)
__device__ float g_qkv  [(size_t)65536 * 768];     // 201 MB
__device__ float g_fconv[(size_t)4 * 864 * LSP];   // 226 MB
__device__ float g_attn [(size_t)65536 * 256];     //  67 MB

// ---------------------------------------------------------------------------
// Generic SIMT GEMM: C[M,N] = A[M,K] @ B[K,N], fp32, 128x128x16 tile,
// 256 threads, 8x8 per thread. MODE 0: plain store. MODE 1: proj epilogue
// (window-reverse scatter + d_out += alpha*(acc + bias)).
// M % 128 == 0, N % 128 == 0, K % 16 == 0 (holds for both uses).
// ---------------------------------------------------------------------------
template<int MODE>
__global__ __launch_bounds__(256) void gemm_kernel(
    const float* __restrict__ A, const float* __restrict__ B,
    float* __restrict__ C, int M, int N, int K,
    const float* __restrict__ bias, const float* __restrict__ alpha_p)
{
    __shared__ float As[16][132];   // transposed, padded
    __shared__ float Bs[16][128];

    const int tid = threadIdx.x;
    const int bc = blockIdx.x, br = blockIdx.y;
    const float* Ab = A + (size_t)br * 128 * K;
    const float* Bb = B + (size_t)bc * 128;

    float acc[8][8];
#pragma unroll
    for (int i = 0; i < 8; i++)
#pragma unroll
        for (int j = 0; j < 8; j++) acc[i][j] = 0.f;

    const int ty = tid >> 4, tx = tid & 15;

    for (int k0 = 0; k0 < K; k0 += 16) {
#pragma unroll
        for (int i = 0; i < 2; i++) {
            int idx = tid + i * 256;          // 0..511
            int m = idx >> 2, k4 = idx & 3;
            float4 v = *reinterpret_cast<const float4*>(Ab + (size_t)m * K + k0 + k4 * 4);
            As[k4 * 4 + 0][m] = v.x; As[k4 * 4 + 1][m] = v.y;
            As[k4 * 4 + 2][m] = v.z; As[k4 * 4 + 3][m] = v.w;
        }
#pragma unroll
        for (int i = 0; i < 2; i++) {
            int idx = tid + i * 256;
            int kk = idx >> 5, n4 = idx & 31;
            *reinterpret_cast<float4*>(&Bs[kk][n4 * 4]) =
                *reinterpret_cast<const float4*>(Bb + (size_t)(k0 + kk) * N + n4 * 4);
        }
        __syncthreads();
#pragma unroll
        for (int kk = 0; kk < 16; kk++) {
            float ra[8], rb[8];
            float4 a0 = *reinterpret_cast<const float4*>(&As[kk][ty * 8]);
            float4 a1 = *reinterpret_cast<const float4*>(&As[kk][ty * 8 + 4]);
            ra[0] = a0.x; ra[1] = a0.y; ra[2] = a0.z; ra[3] = a0.w;
            ra[4] = a1.x; ra[5] = a1.y; ra[6] = a1.z; ra[7] = a1.w;
            float4 b0 = *reinterpret_cast<const float4*>(&Bs[kk][tx * 8]);
            float4 b1 = *reinterpret_cast<const float4*>(&Bs[kk][tx * 8 + 4]);
            rb[0] = b0.x; rb[1] = b0.y; rb[2] = b0.z; rb[3] = b0.w;
            rb[4] = b1.x; rb[5] = b1.y; rb[6] = b1.z; rb[7] = b1.w;
#pragma unroll
            for (int i = 0; i < 8; i++)
#pragma unroll
                for (int j = 0; j < 8; j++)
                    acc[i][j] = fmaf(ra[i], rb[j], acc[i][j]);
        }
        __syncthreads();
    }

    if (MODE == 0) {
#pragma unroll
        for (int i = 0; i < 8; i++) {
            size_t row = (size_t)br * 128 + ty * 8 + i;
            float* dst = C + row * N + bc * 128 + tx * 8;
            *reinterpret_cast<float4*>(dst)     = make_float4(acc[i][0], acc[i][1], acc[i][2], acc[i][3]);
            *reinterpret_cast<float4*>(dst + 4) = make_float4(acc[i][4], acc[i][5], acc[i][6], acc[i][7]);
        }
    } else {
        const float alpha = alpha_p[0];
        const int colbase = bc * 128 + tx * 8;
        float pb[8];
#pragma unroll
        for (int j = 0; j < 8; j++) pb[j] = bias[colbase + j];
#pragma unroll
        for (int i = 0; i < 8; i++) {
            int row = br * 128 + ty * 8 + i;       // win*64 + tok
            int win = row >> 6, tok = row & 63;
            int b = win >> 8, r2 = win & 255;
            int dblk = r2 >> 6, h2 = r2 & 63, hblk = h2 >> 3, wblk = h2 & 7;
            int z4 = tok >> 4, y4 = (tok >> 2) & 3, x4 = tok & 3;
            size_t spat = (((size_t)b * 16 + dblk * 4 + z4) * 32 + hblk * 4 + y4) * 32
                          + wblk * 4 + x4;
            float* dst = C + spat * 256 + colbase;
            float4 e0 = *reinterpret_cast<float4*>(dst);
            float4 e1 = *reinterpret_cast<float4*>(dst + 4);
            e0.x += alpha * (acc[i][0] + pb[0]); e0.y += alpha * (acc[i][1] + pb[1]);
            e0.z += alpha * (acc[i][2] + pb[2]); e0.w += alpha * (acc[i][3] + pb[3]);
            e1.x += alpha * (acc[i][4] + pb[4]); e1.y += alpha * (acc[i][5] + pb[5]);
            e1.z += alpha * (acc[i][6] + pb[6]); e1.w += alpha * (acc[i][7] + pb[7]);
            *reinterpret_cast<float4*>(dst)     = e0;
            *reinterpret_cast<float4*>(dst + 4) = e1;
        }
    }
}

// ---------------------------------------------------------------------------
// fconv: f_conv[b, x*27+o, l] = sum_g fc_w[o,g] * qkv_flat_b[g*524288 + l*32 + x]
//        + fc_b[o]
// Block: 1024 threads = (l_tile 32) x (x 32). Coalesced reads; smem transpose
// so the [channel][l] writes are coalesced too.
// ---------------------------------------------------------------------------
__global__ __launch_bounds__(1024) void fconv_kernel(
    const float* __restrict__ fcw, const float* __restrict__ fcb)
{
    __shared__ float s_fcw[27 * 24];
    __shared__ float s_fcb[27];
    __shared__ float s_out[32 * 9 * 33];   // [x][o_chunk 9][l 32+pad]

    const int tid = threadIdx.x;
    const int b  = blockIdx.y;
    const int l0 = blockIdx.x * 32;

    if (tid < 648) s_fcw[tid] = fcw[tid];
    if (tid < 27)  s_fcb[tid] = fcb[tid];
    __syncthreads();

    const float* qb = g_qkv + (size_t)b * 12582912;   // 16384*768
    float acc[27];
#pragma unroll
    for (int o = 0; o < 27; o++) acc[o] = s_fcb[o];

#pragma unroll 4
    for (int g = 0; g < 24; g++) {
        float v = qb[(size_t)g * 524288 + (size_t)l0 * 32 + tid];
#pragma unroll
        for (int o = 0; o < 27; o++) acc[o] = fmaf(s_fcw[o * 24 + g], v, acc[o]);
    }

    const int xx = tid & 31, ll = tid >> 5;
    float* fco = g_fconv + (size_t)b * 864 * LSP;
#pragma unroll
    for (int r = 0; r < 3; r++) {
#pragma unroll
        for (int oo = 0; oo < 9; oo++)
            s_out[(xx * 9 + oo) * 33 + ll] = acc[r * 9 + oo];
        __syncthreads();
#pragma unroll
        for (int it = 0; it < 9; it++) {
            int e = it * 1024 + tid;        // 0..9215
            int l = e & 31;
            int rest = e >> 5;              // 0..287
            int o  = rest % 9;
            int x2 = rest / 9;
            fco[(size_t)(x2 * 27 + r * 9 + o) * LSP + l0 + l] =
                s_out[(x2 * 9 + o) * 33 + l];
        }
        __syncthreads();
    }
}

// ---------------------------------------------------------------------------
// Grouped conv (32 groups, 27 -> 8 channels, 3x3x3, pad 1) + dep_b, scaled by
// beta, written to d_out in [b, spatial, 256] (channel-last) layout.
// Block: (ytile of 8, z, b*32+g). 256 threads = 8 xq x 4 ocp x 8 y.
// Each thread: 2 oc x 4 x outputs -> 0.5 LDS per FMA.
// ---------------------------------------------------------------------------
#define CONV_SW_FLOATS  (27 * 3 * 10 * 36)            // 29160
#define CONV_SDEP_FLOATS (8 * 729)                    // 5832
#define CONV_SMEM_BYTES ((CONV_SW_FLOATS + CONV_SDEP_FLOATS) * 4)

__global__ __launch_bounds__(256) void conv_kernel(
    const float* __restrict__ dep_w, const float* __restrict__ dep_b,
    const float* __restrict__ beta_p, float* __restrict__ out)
{
    extern __shared__ float sm[];
    float* sw   = sm;                     // [k27][dz3][y10][x36]
    float* sdep = sm + CONV_SW_FLOATS;    // [oc8][729]

    const int tid = threadIdx.x;
    const int y0 = blockIdx.x * 8;
    const int z  = blockIdx.y;
    const int bg = blockIdx.z;
    const int b = bg >> 5, g = bg & 31;

    for (int e = tid; e < 8 * 729; e += 256)
        sdep[e] = dep_w[(size_t)(g * 8) * 729 + e];

    const float* fin = g_fconv + ((size_t)(b * 864 + g * 27)) * LSP;
    for (int e = tid; e < 27 * 3 * 10 * 34; e += 256) {
        int x  = e % 34; int t1 = e / 34;
        int yy = t1 % 10; int t2 = t1 / 10;
        int dz = t2 % 3;  int k  = t2 / 3;
        int gx = x - 1, gy = y0 + yy - 1, gz = z + dz - 1;
        float v = 0.f;
        if (gx >= 0 && gx < 32 && gy >= 0 && gy < 32 && gz >= 0 && gz < 16)
            v = fin[(size_t)k * LSP + gz * 1024 + gy * 32 + gx];
        sw[((k * 3 + dz) * 10 + yy) * 36 + x] = v;
    }
    __syncthreads();

    const int xq  = tid & 7;
    const int ocp = (tid >> 3) & 3;
    const int yy  = tid >> 5;
    const int oc0 = ocp * 2;

    float acc0[4] = {0, 0, 0, 0}, acc1[4] = {0, 0, 0, 0};

#pragma unroll 1
    for (int k = 0; k < 27; k++) {
#pragma unroll
        for (int dz = 0; dz < 3; dz++) {
#pragma unroll
            for (int dy = 0; dy < 3; dy++) {
                const float* wrow = &sw[((k * 3 + dz) * 10 + yy + dy) * 36 + xq * 4];
                float4 wa = *reinterpret_cast<const float4*>(wrow);
                float2 wb = *reinterpret_cast<const float2*>(wrow + 4);
                float win[6] = {wa.x, wa.y, wa.z, wa.w, wb.x, wb.y};
                const float* d0 = &sdep[oc0 * 729 + k * 27 + dz * 9 + dy * 3];
                const float* d1 = d0 + 729;
#pragma unroll
                for (int dx = 0; dx < 3; dx++) {
                    float w0 = d0[dx], w1 = d1[dx];
#pragma unroll
                    for (int c = 0; c < 4; c++) {
                        acc0[c] = fmaf(win[c + dx], w0, acc0[c]);
                        acc1[c] = fmaf(win[c + dx], w1, acc1[c]);
                    }
                }
            }
        }
    }

    const float beta = beta_p[0];
    const int ocg0 = g * 8 + oc0;
    const float b0 = dep_b[ocg0], b1 = dep_b[ocg0 + 1];
    const size_t spatbase = (size_t)b * LSP + z * 1024 + (y0 + yy) * 32 + xq * 4;
#pragma unroll
    for (int c = 0; c < 4; c++) {
        float2 v = make_float2(beta * (acc0[c] + b0), beta * (acc1[c] + b1));
        *reinterpret_cast<float2*>(out + (spatbase + c) * 256 + ocg0) = v;
    }
}

// ---------------------------------------------------------------------------
// Windowed attention: one block per (window, head). n=64 tokens, hd=32.
// Rel-pos bias computed from token coords, table preloaded per head.
// ---------------------------------------------------------------------------
__global__ __launch_bounds__(256) void attn_kernel(const float* __restrict__ rpb)
{
    __shared__ float sq[64][36];
    __shared__ float sk[64][36];
    __shared__ float sv[64][36];
    __shared__ float sS[64][65];
    __shared__ float sbias[343];

    const int tid = threadIdx.x;
    const int win = blockIdx.x, head = blockIdx.y;
    const int b = win >> 8, r2 = win & 255;
    const int dblk = r2 >> 6, h2 = r2 & 63, hblk = h2 >> 3, wblk = h2 & 7;

    for (int i = tid; i < 343; i += 256) sbias[i] = rpb[i * 8 + head];

    for (int e = tid; e < 64 * 32; e += 256) {
        int tok = e >> 5, dd = e & 31;
        int z = tok >> 4, y = (tok >> 2) & 3, x = tok & 3;
        size_t spat = (((size_t)b * 16 + dblk * 4 + z) * 32 + hblk * 4 + y) * 32
                      + wblk * 4 + x;
        const float* src = g_qkv + spat * 768 + head * 32 + dd;
        sq[tok][dd] = src[0];
        sk[tok][dd] = src[256];
        sv[tok][dd] = src[512];
    }
    __syncthreads();

    const int i  = tid >> 2;    // row 0..63
    const int jg = tid & 3;     // 4 lanes per row

    float qreg[32];
#pragma unroll
    for (int d4 = 0; d4 < 8; d4++) {
        float4 q4 = *reinterpret_cast<const float4*>(&sq[i][d4 * 4]);
        qreg[d4 * 4 + 0] = q4.x; qreg[d4 * 4 + 1] = q4.y;
        qreg[d4 * 4 + 2] = q4.z; qreg[d4 * 4 + 3] = q4.w;
    }
    const float scale = 0.17677669529663687f;   // 32^-0.5
    const int zi = i >> 4, yi = (i >> 2) & 3, xi = i & 3;

    float se[16];
    float rowmax = -1e30f;
#pragma unroll
    for (int jj = 0; jj < 16; jj++) {
        int j = jg * 16 + jj;
        float dot = 0.f;
#pragma unroll
        for (int d4 = 0; d4 < 8; d4++) {
            float4 kv = *reinterpret_cast<const float4*>(&sk[j][d4 * 4]);
            dot = fmaf(qreg[d4 * 4 + 0], kv.x, dot);
            dot = fmaf(qreg[d4 * 4 + 1], kv.y, dot);
            dot = fmaf(qreg[d4 * 4 + 2], kv.z, dot);
            dot = fmaf(qreg[d4 * 4 + 3], kv.w, dot);
        }
        int zj = j >> 4, yj = (j >> 2) & 3, xj = j & 3;
        int rel = (zi - zj + 3) * 49 + (yi - yj + 3) * 7 + (xi - xj + 3);
        float s = dot * scale + sbias[rel];
        se[jj] = s;
        rowmax = fmaxf(rowmax, s);
    }
    rowmax = fmaxf(rowmax, __shfl_xor_sync(0xffffffffu, rowmax, 1));
    rowmax = fmaxf(rowmax, __shfl_xor_sync(0xffffffffu, rowmax, 2));

    float rsum = 0.f;
#pragma unroll
    for (int jj = 0; jj < 16; jj++) {
        float ev = __expf(se[jj] - rowmax);
        se[jj] = ev;
        rsum += ev;
    }
    rsum += __shfl_xor_sync(0xffffffffu, rsum, 1);
    rsum += __shfl_xor_sync(0xffffffffu, rsum, 2);
    const float inv = 1.f / rsum;
#pragma unroll
    for (int jj = 0; jj < 16; jj++)
        sS[i][jg * 16 + jj] = se[jj] * inv;
    __syncthreads();

    // O[i][dg*8 .. +8] = sum_j P[i][j] * v[j][:]
    const int dg = tid & 3;
    float o[8] = {0, 0, 0, 0, 0, 0, 0, 0};
    for (int j = 0; j < 64; j++) {
        float p = sS[i][j];
        float4 v0 = *reinterpret_cast<const float4*>(&sv[j][dg * 8]);
        float4 v1 = *reinterpret_cast<const float4*>(&sv[j][dg * 8 + 4]);
        o[0] = fmaf(p, v0.x, o[0]); o[1] = fmaf(p, v0.y, o[1]);
        o[2] = fmaf(p, v0.z, o[2]); o[3] = fmaf(p, v0.w, o[3]);
        o[4] = fmaf(p, v1.x, o[4]); o[5] = fmaf(p, v1.y, o[5]);
        o[6] = fmaf(p, v1.z, o[6]); o[7] = fmaf(p, v1.w, o[7]);
    }
    float* dst = g_attn + ((size_t)win * 64 + i) * 256 + head * 32 + dg * 8;
    *reinterpret_cast<float4*>(dst)     = make_float4(o[0], o[1], o[2], o[3]);
    *reinterpret_cast<float4*>(dst + 4) = make_float4(o[4], o[5], o[6], o[7]);
}

// ---------------------------------------------------------------------------
// Launch
// ---------------------------------------------------------------------------
extern "C" void kernel_launch(void* const* d_in, const int* in_sizes, int n_in,
                              void* d_out, int out_size)
{
    (void)in_sizes; (void)n_in; (void)out_size;
    const float* x_in   = (const float*)d_in[0];
    const float* qkv_w  = (const float*)d_in[1];
    const float* proj_w = (const float*)d_in[2];
    const float* proj_b = (const float*)d_in[3];
    const float* rpb    = (const float*)d_in[4];
    const float* fc_w   = (const float*)d_in[5];
    const float* fc_b   = (const float*)d_in[6];
    const float* dep_w  = (const float*)d_in[7];
    const float* dep_b  = (const float*)d_in[8];
    const float* alpha  = (const float*)d_in[9];
    const float* beta   = (const float*)d_in[10];
    float* out = (float*)d_out;

    float *p_qkv, *p_attn;
    cudaGetSymbolAddress((void**)&p_qkv, g_qkv);
    cudaGetSymbolAddress((void**)&p_attn, g_attn);

    // 1) qkv = x_in @ qkv_w   [65536,256]x[256,768]
    gemm_kernel<0><<<dim3(6, 512), 256>>>(x_in, qkv_w, p_qkv,
                                          65536, 768, 256, nullptr, nullptr);
    // 2) f_conv (1x1 conv on the raw-reshaped qkv)
    fconv_kernel<<<dim3(512, 4), 1024>>>(fc_w, fc_b);
    // 3) grouped 3x3x3 conv -> d_out = beta*(conv + dep_b)
    cudaFuncSetAttribute(conv_kernel, cudaFuncAttributeMaxDynamicSharedMemorySize,
                         CONV_SMEM_BYTES);
    conv_kernel<<<dim3(4, 16, 128), 256, CONV_SMEM_BYTES>>>(dep_w, dep_b, beta, out);
    // 4) windowed attention -> g_attn
    attn_kernel<<<dim3(1024, 8), 256>>>(rpb);
    // 5) proj + window-reverse + d_out += alpha*(...)
    gemm_kernel<1><<<dim3(2, 512), 256>>>(p_attn, proj_w, out,
                                          65536, 256, 256, proj_b, alpha);
}

// round 4
// speedup vs baseline: 1.2815x; 1.2815x over previous
#include <cuda_runtime.h>
#include <cuda_bf16.h>
#include <stdint.h>
#include <math.h>

typedef unsigned int u32;

// ---------------------------------------------------------------------------
// Problem constants
//   x_in [4,16,32,32,256], qkv_w [256,768], proj_w [256,256], proj_b [256]
//   rpb_table [343,8], fc_w [27,24], fc_b [27], dep_w [256,27,3,3,3],
//   dep_b [256], alpha, beta; out [4,16,32,32,256] float32
// ---------------------------------------------------------------------------
#define LSP 16384

__device__ float g_qkv  [(size_t)65536 * 768];
__device__ float g_fconv[(size_t)4 * 864 * LSP];
__device__ float g_attn [(size_t)65536 * 256];

__device__ __forceinline__ u32 smem_u32(const void* p) {
    return (u32)__cvta_generic_to_shared(p);
}

__device__ __forceinline__ void ldsm_x4(u32& r0, u32& r1, u32& r2, u32& r3, u32 a) {
    asm volatile("ldmatrix.sync.aligned.m8n8.x4.shared.b16 {%0,%1,%2,%3}, [%4];\n"
                 : "=r"(r0), "=r"(r1), "=r"(r2), "=r"(r3) : "r"(a));
}

__device__ __forceinline__ void ldsm_x4t(u32& r0, u32& r1, u32& r2, u32& r3, u32 a) {
    asm volatile("ldmatrix.sync.aligned.m8n8.x4.trans.shared.b16 {%0,%1,%2,%3}, [%4];\n"
                 : "=r"(r0), "=r"(r1), "=r"(r2), "=r"(r3) : "r"(a));
}

__device__ __forceinline__ void mma_bf16(float* c, const u32* a, const u32* b) {
    asm volatile(
        "mma.sync.aligned.m16n8k16.row.col.f32.bf16.bf16.f32 "
        "{%0,%1,%2,%3}, {%4,%5,%6,%7}, {%8,%9}, {%0,%1,%2,%3};\n"
        : "+f"(c[0]), "+f"(c[1]), "+f"(c[2]), "+f"(c[3])
        : "r"(a[0]), "r"(a[1]), "r"(a[2]), "r"(a[3]), "r"(b[0]), "r"(b[1]));
}

__device__ __forceinline__ float warp16_max(float v) {
    v = fmaxf(v, __shfl_xor_sync(0xffffffffu, v, 1));
    v = fmaxf(v, __shfl_xor_sync(0xffffffffu, v, 2));
    v = fmaxf(v, __shfl_xor_sync(0xffffffffu, v, 4));
    v = fmaxf(v, __shfl_xor_sync(0xffffffffu, v, 8));
    return v;
}

__device__ __forceinline__ float warp16_sum(float v) {
    v += __shfl_xor_sync(0xffffffffu, v, 1);
    v += __shfl_xor_sync(0xffffffffu, v, 2);
    v += __shfl_xor_sync(0xffffffffu, v, 4);
    v += __shfl_xor_sync(0xffffffffu, v, 8);
    return v;
}

// ---------------------------------------------------------------------------
// Tensor-core GEMM with bf16 3-term split: C = Ah@Bh + Ah@Bl + Al@Bh.
// 128x128x32 tile, 256 threads, 8 warps (2 in M, 4 in N), 64x32 per warp.
// MODE 0: plain store. MODE 1: window-reverse + out += alpha*(acc+bias).
// ---------------------------------------------------------------------------
template<int MODE>
__global__ __launch_bounds__(256) void gemm_bf16(
    const float* __restrict__ A, const float* __restrict__ B,
    float* __restrict__ C, int M, int N, int K,
    const float* __restrict__ bias, const float* __restrict__ alpha_p)
{
    __shared__ __align__(16) __nv_bfloat16 sAh[128][40];
    __shared__ __align__(16) __nv_bfloat16 sAl[128][40];
    __shared__ __align__(16) __nv_bfloat16 sBh[32][136];
    __shared__ __align__(16) __nv_bfloat16 sBl[32][136];

    const int tid = threadIdx.x;
    const int lane = tid & 31;
    const int wid = tid >> 5;
    const int wm = (wid & 1) * 64;
    const int wn = (wid >> 1) * 32;
    const int bm = blockIdx.y * 128;
    const int bn = blockIdx.x * 128;

    float acc[4][4][4];
#pragma unroll
    for (int i = 0; i < 4; i++) {
#pragma unroll
        for (int j = 0; j < 4; j++) {
#pragma unroll
            for (int r = 0; r < 4; r++) {
                acc[i][j][r] = 0.0f;
            }
        }
    }

    const int arow = tid >> 3;
    const int akq = tid & 7;
    const int brow = tid >> 5;
    const int bnq = tid & 31;

    float4 av[4];
    float4 bv[4];
    const int nk = K >> 5;

#pragma unroll
    for (int p = 0; p < 4; p++) {
        av[p] = *reinterpret_cast<const float4*>(
            A + (size_t)(bm + p * 32 + arow) * K + akq * 4);
        bv[p] = *reinterpret_cast<const float4*>(
            B + (size_t)(p * 8 + brow) * N + bn + bnq * 4);
    }

    for (int kt = 0; kt < nk; kt++) {
#pragma unroll
        for (int p = 0; p < 4; p++) {
            float fa[4];
            float fb[4];
            fa[0] = av[p].x; fa[1] = av[p].y; fa[2] = av[p].z; fa[3] = av[p].w;
            fb[0] = bv[p].x; fb[1] = bv[p].y; fb[2] = bv[p].z; fb[3] = bv[p].w;
            __nv_bfloat16 ah[4];
            __nv_bfloat16 al[4];
            __nv_bfloat16 bh[4];
            __nv_bfloat16 bl[4];
#pragma unroll
            for (int q = 0; q < 4; q++) {
                ah[q] = __float2bfloat16(fa[q]);
                al[q] = __float2bfloat16(fa[q] - __bfloat162float(ah[q]));
                bh[q] = __float2bfloat16(fb[q]);
                bl[q] = __float2bfloat16(fb[q] - __bfloat162float(bh[q]));
            }
            __nv_bfloat162* dAh = reinterpret_cast<__nv_bfloat162*>(&sAh[p * 32 + arow][akq * 4]);
            __nv_bfloat162* dAl = reinterpret_cast<__nv_bfloat162*>(&sAl[p * 32 + arow][akq * 4]);
            dAh[0] = __halves2bfloat162(ah[0], ah[1]);
            dAh[1] = __halves2bfloat162(ah[2], ah[3]);
            dAl[0] = __halves2bfloat162(al[0], al[1]);
            dAl[1] = __halves2bfloat162(al[2], al[3]);
            __nv_bfloat162* dBh = reinterpret_cast<__nv_bfloat162*>(&sBh[p * 8 + brow][bnq * 4]);
            __nv_bfloat162* dBl = reinterpret_cast<__nv_bfloat162*>(&sBl[p * 8 + brow][bnq * 4]);
            dBh[0] = __halves2bfloat162(bh[0], bh[1]);
            dBh[1] = __halves2bfloat162(bh[2], bh[3]);
            dBl[0] = __halves2bfloat162(bl[0], bl[1]);
            dBl[1] = __halves2bfloat162(bl[2], bl[3]);
        }
        __syncthreads();

        if (kt + 1 < nk) {
#pragma unroll
            for (int p = 0; p < 4; p++) {
                av[p] = *reinterpret_cast<const float4*>(
                    A + (size_t)(bm + p * 32 + arow) * K + (kt + 1) * 32 + akq * 4);
                bv[p] = *reinterpret_cast<const float4*>(
                    B + (size_t)((kt + 1) * 32 + p * 8 + brow) * N + bn + bnq * 4);
            }
        }

        const int a_r = lane & 15;
        const int a_k = (lane >> 4) * 8;

#pragma unroll
        for (int ks = 0; ks < 2; ks++) {
            u32 aH[4][4];
            u32 aL[4][4];
            u32 bH[4][2];
            u32 bL[4][2];
#pragma unroll
            for (int mi = 0; mi < 4; mi++) {
                u32 adr = smem_u32(&sAh[wm + mi * 16 + a_r][ks * 16 + a_k]);
                ldsm_x4(aH[mi][0], aH[mi][1], aH[mi][2], aH[mi][3], adr);
                adr = smem_u32(&sAl[wm + mi * 16 + a_r][ks * 16 + a_k]);
                ldsm_x4(aL[mi][0], aL[mi][1], aL[mi][2], aL[mi][3], adr);
            }
#pragma unroll
            for (int nj = 0; nj < 2; nj++) {
                u32 r0;
                u32 r1;
                u32 r2;
                u32 r3;
                u32 adr = smem_u32(&sBh[ks * 16 + a_r][wn + nj * 16 + a_k]);
                ldsm_x4t(r0, r1, r2, r3, adr);
                bH[nj * 2][0] = r0;
                bH[nj * 2][1] = r1;
                bH[nj * 2 + 1][0] = r2;
                bH[nj * 2 + 1][1] = r3;
                adr = smem_u32(&sBl[ks * 16 + a_r][wn + nj * 16 + a_k]);
                ldsm_x4t(r0, r1, r2, r3, adr);
                bL[nj * 2][0] = r0;
                bL[nj * 2][1] = r1;
                bL[nj * 2 + 1][0] = r2;
                bL[nj * 2 + 1][1] = r3;
            }
#pragma unroll
            for (int mi = 0; mi < 4; mi++) {
#pragma unroll
                for (int ni = 0; ni < 4; ni++) {
                    mma_bf16(acc[mi][ni], aH[mi], bH[ni]);
                    mma_bf16(acc[mi][ni], aH[mi], bL[ni]);
                    mma_bf16(acc[mi][ni], aL[mi], bH[ni]);
                }
            }
        }
        __syncthreads();
    }

    const int g = lane >> 2;
    const int tg = lane & 3;

    if (MODE == 0) {
#pragma unroll
        for (int mi = 0; mi < 4; mi++) {
            int row0 = bm + wm + mi * 16 + g;
#pragma unroll
            for (int ni = 0; ni < 4; ni++) {
                int col = bn + wn + ni * 8 + tg * 2;
                float2 v0;
                float2 v1;
                v0.x = acc[mi][ni][0];
                v0.y = acc[mi][ni][1];
                v1.x = acc[mi][ni][2];
                v1.y = acc[mi][ni][3];
                *reinterpret_cast<float2*>(&C[(size_t)row0 * N + col]) = v0;
                *reinterpret_cast<float2*>(&C[(size_t)(row0 + 8) * N + col]) = v1;
            }
        }
    } else {
        const float alpha = alpha_p[0];
#pragma unroll
        for (int mi = 0; mi < 4; mi++) {
#pragma unroll
            for (int half = 0; half < 2; half++) {
                int row = bm + wm + mi * 16 + g + half * 8;
                int win = row >> 6;
                int tok = row & 63;
                int b = win >> 8;
                int r2 = win & 255;
                int dblk = r2 >> 6;
                int h2 = r2 & 63;
                int hblk = h2 >> 3;
                int wblk = h2 & 7;
                int z4 = tok >> 4;
                int y4 = (tok >> 2) & 3;
                int x4 = tok & 3;
                size_t spat = (((size_t)b * 16 + dblk * 4 + z4) * 32 + hblk * 4 + y4) * 32
                              + wblk * 4 + x4;
#pragma unroll
                for (int ni = 0; ni < 4; ni++) {
                    int col = bn + wn + ni * 8 + tg * 2;
                    float2 pb = *reinterpret_cast<const float2*>(&bias[col]);
                    float* dst = &C[spat * 256 + col];
                    float2 e = *reinterpret_cast<float2*>(dst);
                    e.x += alpha * (acc[mi][ni][half * 2 + 0] + pb.x);
                    e.y += alpha * (acc[mi][ni][half * 2 + 1] + pb.y);
                    *reinterpret_cast<float2*>(dst) = e;
                }
            }
        }
    }
}

// ---------------------------------------------------------------------------
// fconv
// ---------------------------------------------------------------------------
__global__ __launch_bounds__(1024) void fconv_kernel(
    const float* __restrict__ fcw, const float* __restrict__ fcb)
{
    __shared__ float s_fcw[27 * 24];
    __shared__ float s_fcb[27];
    __shared__ float s_out[32 * 9 * 33];

    const int tid = threadIdx.x;
    const int b = blockIdx.y;
    const int l0 = blockIdx.x * 32;

    if (tid < 648) {
        s_fcw[tid] = fcw[tid];
    }
    if (tid < 27) {
        s_fcb[tid] = fcb[tid];
    }
    __syncthreads();

    const float* qb = g_qkv + (size_t)b * 12582912;
    float acc[27];
#pragma unroll
    for (int o = 0; o < 27; o++) {
        acc[o] = s_fcb[o];
    }

#pragma unroll 4
    for (int g = 0; g < 24; g++) {
        float v = qb[(size_t)g * 524288 + (size_t)l0 * 32 + tid];
#pragma unroll
        for (int o = 0; o < 27; o++) {
            acc[o] = fmaf(s_fcw[o * 24 + g], v, acc[o]);
        }
    }

    const int xx = tid & 31;
    const int ll = tid >> 5;
    float* fco = g_fconv + (size_t)b * 864 * LSP;
#pragma unroll
    for (int r = 0; r < 3; r++) {
#pragma unroll
        for (int oo = 0; oo < 9; oo++) {
            s_out[(xx * 9 + oo) * 33 + ll] = acc[r * 9 + oo];
        }
        __syncthreads();
#pragma unroll
        for (int it = 0; it < 9; it++) {
            int e = it * 1024 + tid;
            int l = e & 31;
            int rest = e >> 5;
            int o = rest % 9;
            int x2 = rest / 9;
            fco[(size_t)(x2 * 27 + r * 9 + o) * LSP + l0 + l] =
                s_out[(x2 * 9 + o) * 33 + l];
        }
        __syncthreads();
    }
}

// ---------------------------------------------------------------------------
// Grouped conv (32 groups, 27->8 ch, 3x3x3, pad 1) + dep_b, *beta -> d_out
// ---------------------------------------------------------------------------
#define CONV_SW_FLOATS  (27 * 3 * 10 * 36)
#define CONV_SDEP_FLOATS (8 * 729)
#define CONV_SMEM_BYTES ((CONV_SW_FLOATS + CONV_SDEP_FLOATS) * 4)

__global__ __launch_bounds__(256) void conv_kernel(
    const float* __restrict__ dep_w, const float* __restrict__ dep_b,
    const float* __restrict__ beta_p, float* __restrict__ out)
{
    extern __shared__ float sm[];
    float* sw = sm;
    float* sdep = sm + CONV_SW_FLOATS;

    const int tid = threadIdx.x;
    const int y0 = blockIdx.x * 8;
    const int z = blockIdx.y;
    const int bg = blockIdx.z;
    const int b = bg >> 5;
    const int g = bg & 31;

    for (int e = tid; e < 8 * 729; e += 256) {
        sdep[e] = dep_w[(size_t)(g * 8) * 729 + e];
    }

    const float* fin = g_fconv + ((size_t)(b * 864 + g * 27)) * LSP;
    for (int e = tid; e < 27 * 3 * 10 * 34; e += 256) {
        int x = e % 34;
        int t1 = e / 34;
        int yy = t1 % 10;
        int t2 = t1 / 10;
        int dz = t2 % 3;
        int k = t2 / 3;
        int gx = x - 1;
        int gy = y0 + yy - 1;
        int gz = z + dz - 1;
        float v = 0.0f;
        if (gx >= 0 && gx < 32 && gy >= 0 && gy < 32 && gz >= 0 && gz < 16) {
            v = fin[(size_t)k * LSP + gz * 1024 + gy * 32 + gx];
        }
        sw[((k * 3 + dz) * 10 + yy) * 36 + x] = v;
    }
    __syncthreads();

    const int xq = tid & 7;
    const int ocp = (tid >> 3) & 3;
    const int yy = tid >> 5;
    const int oc0 = ocp * 2;

    float acc0[4] = {0.0f, 0.0f, 0.0f, 0.0f};
    float acc1[4] = {0.0f, 0.0f, 0.0f, 0.0f};

#pragma unroll 1
    for (int k = 0; k < 27; k++) {
#pragma unroll
        for (int dz = 0; dz < 3; dz++) {
#pragma unroll
            for (int dy = 0; dy < 3; dy++) {
                const float* wrow = &sw[((k * 3 + dz) * 10 + yy + dy) * 36 + xq * 4];
                float4 wa = *reinterpret_cast<const float4*>(wrow);
                float2 wb = *reinterpret_cast<const float2*>(wrow + 4);
                float win[6];
                win[0] = wa.x; win[1] = wa.y; win[2] = wa.z; win[3] = wa.w;
                win[4] = wb.x; win[5] = wb.y;
                const float* d0 = &sdep[oc0 * 729 + k * 27 + dz * 9 + dy * 3];
                const float* d1 = d0 + 729;
#pragma unroll
                for (int dx = 0; dx < 3; dx++) {
                    float w0 = d0[dx];
                    float w1 = d1[dx];
#pragma unroll
                    for (int c = 0; c < 4; c++) {
                        acc0[c] = fmaf(win[c + dx], w0, acc0[c]);
                        acc1[c] = fmaf(win[c + dx], w1, acc1[c]);
                    }
                }
            }
        }
    }

    const float beta = beta_p[0];
    const int ocg0 = g * 8 + oc0;
    const float b0 = dep_b[ocg0];
    const float b1 = dep_b[ocg0 + 1];
    const size_t spatbase = (size_t)b * LSP + z * 1024 + (y0 + yy) * 32 + xq * 4;
#pragma unroll
    for (int c = 0; c < 4; c++) {
        float2 v;
        v.x = beta * (acc0[c] + b0);
        v.y = beta * (acc1[c] + b1);
        *reinterpret_cast<float2*>(out + (spatbase + c) * 256 + ocg0) = v;
    }
}

// ---------------------------------------------------------------------------
// Windowed attention, microtiled.
// ---------------------------------------------------------------------------
__global__ __launch_bounds__(256) void attn_kernel(const float* __restrict__ rpb)
{
    __shared__ __align__(16) float sq[64][36];
    __shared__ __align__(16) float skT[32][68];
    __shared__ __align__(16) float sv[64][36];
    __shared__ __align__(16) float sS[64][68];
    __shared__ float sbias[343];

    const int tid = threadIdx.x;
    const int win = blockIdx.x;
    const int head = blockIdx.y;
    const int b = win >> 8;
    const int rr = win & 255;
    const int dblk = rr >> 6;
    const int h2 = rr & 63;
    const int hblk = h2 >> 3;
    const int wblk = h2 & 7;

    for (int i = tid; i < 343; i += 256) {
        sbias[i] = rpb[i * 8 + head];
    }

    for (int e = tid; e < 64 * 32; e += 256) {
        int tok = e >> 5;
        int dd = e & 31;
        int z = tok >> 4;
        int y = (tok >> 2) & 3;
        int x = tok & 3;
        size_t spat = (((size_t)b * 16 + dblk * 4 + z) * 32 + hblk * 4 + y) * 32
                      + wblk * 4 + x;
        const float* src = g_qkv + spat * 768 + head * 32 + dd;
        sq[tok][dd] = src[0];
        skT[dd][tok] = src[256];
        sv[tok][dd] = src[512];
    }
    __syncthreads();

    const int i4 = tid >> 4;
    const int jq = tid & 15;
    const int i0 = i4 * 4;
    const int j0 = jq * 4;

    float dots[4][4];
#pragma unroll
    for (int r = 0; r < 4; r++) {
#pragma unroll
        for (int c = 0; c < 4; c++) {
            dots[r][c] = 0.0f;
        }
    }

#pragma unroll
    for (int d8 = 0; d8 < 4; d8++) {
        float qreg[4][8];
#pragma unroll
        for (int r = 0; r < 4; r++) {
            float4 q0 = *reinterpret_cast<const float4*>(&sq[i0 + r][d8 * 8]);
            float4 q1 = *reinterpret_cast<const float4*>(&sq[i0 + r][d8 * 8 + 4]);
            qreg[r][0] = q0.x; qreg[r][1] = q0.y; qreg[r][2] = q0.z; qreg[r][3] = q0.w;
            qreg[r][4] = q1.x; qreg[r][5] = q1.y; qreg[r][6] = q1.z; qreg[r][7] = q1.w;
        }
#pragma unroll
        for (int dd = 0; dd < 8; dd++) {
            float4 kv = *reinterpret_cast<const float4*>(&skT[d8 * 8 + dd][j0]);
#pragma unroll
            for (int r = 0; r < 4; r++) {
                dots[r][0] = fmaf(qreg[r][dd], kv.x, dots[r][0]);
                dots[r][1] = fmaf(qreg[r][dd], kv.y, dots[r][1]);
                dots[r][2] = fmaf(qreg[r][dd], kv.z, dots[r][2]);
                dots[r][3] = fmaf(qreg[r][dd], kv.w, dots[r][3]);
            }
        }
    }

    const float scale = 0.17677669529663687f;
#pragma unroll
    for (int r = 0; r < 4; r++) {
        int ti = i0 + r;
        int zi = ti >> 4;
        int yi = (ti >> 2) & 3;
        int xi = ti & 3;
        float sv4[4];
#pragma unroll
        for (int c = 0; c < 4; c++) {
            int tj = j0 + c;
            int zj = tj >> 4;
            int yj = (tj >> 2) & 3;
            int xj = tj & 3;
            int rel = (zi - zj + 3) * 49 + (yi - yj + 3) * 7 + (xi - xj + 3);
            sv4[c] = dots[r][c] * scale + sbias[rel];
        }
        float rmax = fmaxf(fmaxf(sv4[0], sv4[1]), fmaxf(sv4[2], sv4[3]));
        rmax = warp16_max(rmax);
        float rsum = 0.0f;
#pragma unroll
        for (int c = 0; c < 4; c++) {
            sv4[c] = __expf(sv4[c] - rmax);
            rsum += sv4[c];
        }
        rsum = warp16_sum(rsum);
        float inv = 1.0f / rsum;
        float4 pv;
        pv.x = sv4[0] * inv;
        pv.y = sv4[1] * inv;
        pv.z = sv4[2] * inv;
        pv.w = sv4[3] * inv;
        *reinterpret_cast<float4*>(&sS[i0 + r][j0]) = pv;
    }
    __syncthreads();

    const int p2 = tid >> 3;
    const int dg = tid & 7;
    const int r0 = p2 * 2;
    const int r1 = r0 + 1;
    float o0[4] = {0.0f, 0.0f, 0.0f, 0.0f};
    float o1[4] = {0.0f, 0.0f, 0.0f, 0.0f};
#pragma unroll 4
    for (int j = 0; j < 64; j++) {
        float4 v = *reinterpret_cast<const float4*>(&sv[j][dg * 4]);
        float pa = sS[r0][j];
        float pbv = sS[r1][j];
        o0[0] = fmaf(pa, v.x, o0[0]);
        o0[1] = fmaf(pa, v.y, o0[1]);
        o0[2] = fmaf(pa, v.z, o0[2]);
        o0[3] = fmaf(pa, v.w, o0[3]);
        o1[0] = fmaf(pbv, v.x, o1[0]);
        o1[1] = fmaf(pbv, v.y, o1[1]);
        o1[2] = fmaf(pbv, v.z, o1[2]);
        o1[3] = fmaf(pbv, v.w, o1[3]);
    }
    float* dst0 = g_attn + ((size_t)win * 64 + r0) * 256 + head * 32 + dg * 4;
    float* dst1 = g_attn + ((size_t)win * 64 + r1) * 256 + head * 32 + dg * 4;
    float4 w0;
    w0.x = o0[0]; w0.y = o0[1]; w0.z = o0[2]; w0.w = o0[3];
    float4 w1;
    w1.x = o1[0]; w1.y = o1[1]; w1.z = o1[2]; w1.w = o1[3];
    *reinterpret_cast<float4*>(dst0) = w0;
    *reinterpret_cast<float4*>(dst1) = w1;
}

// ---------------------------------------------------------------------------
// Launch
// ---------------------------------------------------------------------------
extern "C" void kernel_launch(void* const* d_in, const int* in_sizes, int n_in,
                              void* d_out, int out_size)
{
    (void)in_sizes;
    (void)n_in;
    (void)out_size;
    const float* x_in   = (const float*)d_in[0];
    const float* qkv_w  = (const float*)d_in[1];
    const float* proj_w = (const float*)d_in[2];
    const float* proj_b = (const float*)d_in[3];
    const float* rpb    = (const float*)d_in[4];
    const float* fc_w   = (const float*)d_in[5];
    const float* fc_b   = (const float*)d_in[6];
    const float* dep_w  = (const float*)d_in[7];
    const float* dep_b  = (const float*)d_in[8];
    const float* alpha  = (const float*)d_in[9];
    const float* beta   = (const float*)d_in[10];
    float* out = (float*)d_out;

    float* p_qkv;
    float* p_attn;
    cudaGetSymbolAddress((void**)&p_qkv, g_qkv);
    cudaGetSymbolAddress((void**)&p_attn, g_attn);

    gemm_bf16<0><<<dim3(6, 512), 256>>>(x_in, qkv_w, p_qkv,
                                        65536, 768, 256, (const float*)0, (const float*)0);
    fconv_kernel<<<dim3(512, 4), 1024>>>(fc_w, fc_b);
    cudaFuncSetAttribute(conv_kernel, cudaFuncAttributeMaxDynamicSharedMemorySize,
                         CONV_SMEM_BYTES);
    conv_kernel<<<dim3(4, 16, 128), 256, CONV_SMEM_BYTES>>>(dep_w, dep_b, beta, out);
    attn_kernel<<<dim3(1024, 8), 256>>>(rpb);
    gemm_bf16<1><<<dim3(2, 512), 256>>>(p_attn, proj_w, out,
                                        65536, 256, 256, proj_b, alpha);
}

// round 5
// speedup vs baseline: 1.6645x; 1.2989x over previous
#include <cuda_runtime.h>
#include <cuda_bf16.h>
#include <stdint.h>
#include <math.h>

typedef unsigned int u32;

// ---------------------------------------------------------------------------
// x_in [4,16,32,32,256], qkv_w [256,768], proj_w [256,256], proj_b [256]
// rpb_table [343,8], fc_w [27,24], fc_b [27], dep_w [256,27,3,3,3],
// dep_b [256], alpha, beta; out [4,16,32,32,256] float32
// ---------------------------------------------------------------------------
#define LSP 16384

__device__ float g_qkv  [(size_t)65536 * 768];
__device__ float g_fconv[(size_t)4 * 864 * LSP];

__device__ __nv_bfloat16 g_xh[(size_t)65536 * 256];
__device__ __nv_bfloat16 g_xl[(size_t)65536 * 256];
__device__ __nv_bfloat16 g_ah[(size_t)65536 * 256];
__device__ __nv_bfloat16 g_al[(size_t)65536 * 256];
__device__ __nv_bfloat16 g_wqh[256 * 768];
__device__ __nv_bfloat16 g_wql[256 * 768];
__device__ __nv_bfloat16 g_pwh[256 * 256];
__device__ __nv_bfloat16 g_pwl[256 * 256];

__device__ __forceinline__ u32 smem_u32(const void* p) {
    return (u32)__cvta_generic_to_shared(p);
}

__device__ __forceinline__ void ldsm_x4(u32& r0, u32& r1, u32& r2, u32& r3, u32 a) {
    asm volatile("ldmatrix.sync.aligned.m8n8.x4.shared.b16 {%0,%1,%2,%3}, [%4];\n"
                 : "=r"(r0), "=r"(r1), "=r"(r2), "=r"(r3) : "r"(a));
}

__device__ __forceinline__ void ldsm_x4t(u32& r0, u32& r1, u32& r2, u32& r3, u32 a) {
    asm volatile("ldmatrix.sync.aligned.m8n8.x4.trans.shared.b16 {%0,%1,%2,%3}, [%4];\n"
                 : "=r"(r0), "=r"(r1), "=r"(r2), "=r"(r3) : "r"(a));
}

__device__ __forceinline__ void mma_bf16(float* c, const u32* a, const u32* b) {
    asm volatile(
        "mma.sync.aligned.m16n8k16.row.col.f32.bf16.bf16.f32 "
        "{%0,%1,%2,%3}, {%4,%5,%6,%7}, {%8,%9}, {%0,%1,%2,%3};\n"
        : "+f"(c[0]), "+f"(c[1]), "+f"(c[2]), "+f"(c[3])
        : "r"(a[0]), "r"(a[1]), "r"(a[2]), "r"(a[3]), "r"(b[0]), "r"(b[1]));
}

__device__ __forceinline__ float warp16_max(float v) {
    v = fmaxf(v, __shfl_xor_sync(0xffffffffu, v, 1));
    v = fmaxf(v, __shfl_xor_sync(0xffffffffu, v, 2));
    v = fmaxf(v, __shfl_xor_sync(0xffffffffu, v, 4));
    v = fmaxf(v, __shfl_xor_sync(0xffffffffu, v, 8));
    return v;
}

__device__ __forceinline__ float warp16_sum(float v) {
    v += __shfl_xor_sync(0xffffffffu, v, 1);
    v += __shfl_xor_sync(0xffffffffu, v, 2);
    v += __shfl_xor_sync(0xffffffffu, v, 4);
    v += __shfl_xor_sync(0xffffffffu, v, 8);
    return v;
}

// ---------------------------------------------------------------------------
// Elementwise fp32 -> (bf16 hi, bf16 lo) split. n4 = element count / 4.
// ---------------------------------------------------------------------------
__global__ __launch_bounds__(256) void split_kernel(
    const float* __restrict__ s, __nv_bfloat16* __restrict__ h,
    __nv_bfloat16* __restrict__ l, int n4)
{
    int i = blockIdx.x * blockDim.x + threadIdx.x;
    if (i >= n4) {
        return;
    }
    float4 v = reinterpret_cast<const float4*>(s)[i];
    __nv_bfloat16 h0 = __float2bfloat16(v.x);
    __nv_bfloat16 h1 = __float2bfloat16(v.y);
    __nv_bfloat16 h2 = __float2bfloat16(v.z);
    __nv_bfloat16 h3 = __float2bfloat16(v.w);
    __nv_bfloat16 l0 = __float2bfloat16(v.x - __bfloat162float(h0));
    __nv_bfloat16 l1 = __float2bfloat16(v.y - __bfloat162float(h1));
    __nv_bfloat16 l2 = __float2bfloat16(v.z - __bfloat162float(h2));
    __nv_bfloat16 l3 = __float2bfloat16(v.w - __bfloat162float(h3));
    __nv_bfloat162* hp = reinterpret_cast<__nv_bfloat162*>(h) + i * 2;
    __nv_bfloat162* lp = reinterpret_cast<__nv_bfloat162*>(l) + i * 2;
    hp[0] = __halves2bfloat162(h0, h1);
    hp[1] = __halves2bfloat162(h2, h3);
    lp[0] = __halves2bfloat162(l0, l1);
    lp[1] = __halves2bfloat162(l2, l3);
}

// ---------------------------------------------------------------------------
// Tensor-core GEMM on pre-split bf16 inputs: C = Ah@Bh + Ah@Bl + Al@Bh.
// 128x128x32 tile, 256 threads, 8 warps (2 in M, 4 in N), 64x32 per warp.
// MODE 0: plain fp32 store. MODE 1: window-reverse + out += alpha*(acc+bias).
// ---------------------------------------------------------------------------
template<int MODE>
__global__ __launch_bounds__(256) void gemm_bf16(
    const __nv_bfloat16* __restrict__ Ah, const __nv_bfloat16* __restrict__ Al,
    const __nv_bfloat16* __restrict__ Bh, const __nv_bfloat16* __restrict__ Bl,
    float* __restrict__ C, int M, int N, int K,
    const float* __restrict__ bias, const float* __restrict__ alpha_p)
{
    __shared__ __align__(16) __nv_bfloat16 sAh[128][40];
    __shared__ __align__(16) __nv_bfloat16 sAl[128][40];
    __shared__ __align__(16) __nv_bfloat16 sBh[32][136];
    __shared__ __align__(16) __nv_bfloat16 sBl[32][136];

    const int tid = threadIdx.x;
    const int lane = tid & 31;
    const int wid = tid >> 5;
    const int wm = (wid & 1) * 64;
    const int wn = (wid >> 1) * 32;
    const int bm = blockIdx.y * 128;
    const int bn = blockIdx.x * 128;

    float acc[4][4][4];
#pragma unroll
    for (int i = 0; i < 4; i++) {
#pragma unroll
        for (int j = 0; j < 4; j++) {
#pragma unroll
            for (int r = 0; r < 4; r++) {
                acc[i][j][r] = 0.0f;
            }
        }
    }

    const int nk = K >> 5;
    uint4 rAh[2];
    uint4 rAl[2];
    uint4 rBh[2];
    uint4 rBl[2];

    // prologue: load tile 0
#pragma unroll
    for (int i = 0; i < 2; i++) {
        int u = tid + i * 256;
        int ar = u >> 2;
        int ac = (u & 3) * 8;
        size_t aidx = (size_t)(bm + ar) * K + ac;
        rAh[i] = *reinterpret_cast<const uint4*>(Ah + aidx);
        rAl[i] = *reinterpret_cast<const uint4*>(Al + aidx);
        int br = u >> 4;
        int bc = (u & 15) * 8;
        size_t bidx = (size_t)br * N + bn + bc;
        rBh[i] = *reinterpret_cast<const uint4*>(Bh + bidx);
        rBl[i] = *reinterpret_cast<const uint4*>(Bl + bidx);
    }

    for (int kt = 0; kt < nk; kt++) {
#pragma unroll
        for (int i = 0; i < 2; i++) {
            int u = tid + i * 256;
            int ar = u >> 2;
            int ac = (u & 3) * 8;
            *reinterpret_cast<uint4*>(&sAh[ar][ac]) = rAh[i];
            *reinterpret_cast<uint4*>(&sAl[ar][ac]) = rAl[i];
            int br = u >> 4;
            int bc = (u & 15) * 8;
            *reinterpret_cast<uint4*>(&sBh[br][bc]) = rBh[i];
            *reinterpret_cast<uint4*>(&sBl[br][bc]) = rBl[i];
        }
        __syncthreads();

        if (kt + 1 < nk) {
#pragma unroll
            for (int i = 0; i < 2; i++) {
                int u = tid + i * 256;
                int ar = u >> 2;
                int ac = (u & 3) * 8;
                size_t aidx = (size_t)(bm + ar) * K + (kt + 1) * 32 + ac;
                rAh[i] = *reinterpret_cast<const uint4*>(Ah + aidx);
                rAl[i] = *reinterpret_cast<const uint4*>(Al + aidx);
                int br = u >> 4;
                int bc = (u & 15) * 8;
                size_t bidx = (size_t)((kt + 1) * 32 + br) * N + bn + bc;
                rBh[i] = *reinterpret_cast<const uint4*>(Bh + bidx);
                rBl[i] = *reinterpret_cast<const uint4*>(Bl + bidx);
            }
        }

        const int a_r = lane & 15;
        const int a_k = (lane >> 4) * 8;

#pragma unroll
        for (int ks = 0; ks < 2; ks++) {
            u32 aH[4][4];
            u32 aL[4][4];
            u32 bH[4][2];
            u32 bL[4][2];
#pragma unroll
            for (int mi = 0; mi < 4; mi++) {
                u32 adr = smem_u32(&sAh[wm + mi * 16 + a_r][ks * 16 + a_k]);
                ldsm_x4(aH[mi][0], aH[mi][1], aH[mi][2], aH[mi][3], adr);
                adr = smem_u32(&sAl[wm + mi * 16 + a_r][ks * 16 + a_k]);
                ldsm_x4(aL[mi][0], aL[mi][1], aL[mi][2], aL[mi][3], adr);
            }
#pragma unroll
            for (int nj = 0; nj < 2; nj++) {
                u32 r0;
                u32 r1;
                u32 r2;
                u32 r3;
                u32 adr = smem_u32(&sBh[ks * 16 + a_r][wn + nj * 16 + a_k]);
                ldsm_x4t(r0, r1, r2, r3, adr);
                bH[nj * 2][0] = r0;
                bH[nj * 2][1] = r1;
                bH[nj * 2 + 1][0] = r2;
                bH[nj * 2 + 1][1] = r3;
                adr = smem_u32(&sBl[ks * 16 + a_r][wn + nj * 16 + a_k]);
                ldsm_x4t(r0, r1, r2, r3, adr);
                bL[nj * 2][0] = r0;
                bL[nj * 2][1] = r1;
                bL[nj * 2 + 1][0] = r2;
                bL[nj * 2 + 1][1] = r3;
            }
#pragma unroll
            for (int mi = 0; mi < 4; mi++) {
#pragma unroll
                for (int ni = 0; ni < 4; ni++) {
                    mma_bf16(acc[mi][ni], aH[mi], bH[ni]);
                    mma_bf16(acc[mi][ni], aH[mi], bL[ni]);
                    mma_bf16(acc[mi][ni], aL[mi], bH[ni]);
                }
            }
        }
        __syncthreads();
    }

    const int g = lane >> 2;
    const int tg = lane & 3;

    if (MODE == 0) {
#pragma unroll
        for (int mi = 0; mi < 4; mi++) {
            int row0 = bm + wm + mi * 16 + g;
#pragma unroll
            for (int ni = 0; ni < 4; ni++) {
                int col = bn + wn + ni * 8 + tg * 2;
                float2 v0;
                float2 v1;
                v0.x = acc[mi][ni][0];
                v0.y = acc[mi][ni][1];
                v1.x = acc[mi][ni][2];
                v1.y = acc[mi][ni][3];
                *reinterpret_cast<float2*>(&C[(size_t)row0 * N + col]) = v0;
                *reinterpret_cast<float2*>(&C[(size_t)(row0 + 8) * N + col]) = v1;
            }
        }
    } else {
        const float alpha = alpha_p[0];
#pragma unroll
        for (int mi = 0; mi < 4; mi++) {
#pragma unroll
            for (int half = 0; half < 2; half++) {
                int row = bm + wm + mi * 16 + g + half * 8;
                int win = row >> 6;
                int tok = row & 63;
                int b = win >> 8;
                int r2 = win & 255;
                int dblk = r2 >> 6;
                int h2 = r2 & 63;
                int hblk = h2 >> 3;
                int wblk = h2 & 7;
                int z4 = tok >> 4;
                int y4 = (tok >> 2) & 3;
                int x4 = tok & 3;
                size_t spat = (((size_t)b * 16 + dblk * 4 + z4) * 32 + hblk * 4 + y4) * 32
                              + wblk * 4 + x4;
#pragma unroll
                for (int ni = 0; ni < 4; ni++) {
                    int col = bn + wn + ni * 8 + tg * 2;
                    float2 pb = *reinterpret_cast<const float2*>(&bias[col]);
                    float* dst = &C[spat * 256 + col];
                    float2 e = *reinterpret_cast<float2*>(dst);
                    e.x += alpha * (acc[mi][ni][half * 2 + 0] + pb.x);
                    e.y += alpha * (acc[mi][ni][half * 2 + 1] + pb.y);
                    *reinterpret_cast<float2*>(dst) = e;
                }
            }
        }
    }
}

// ---------------------------------------------------------------------------
// fconv
// ---------------------------------------------------------------------------
__global__ __launch_bounds__(1024) void fconv_kernel(
    const float* __restrict__ fcw, const float* __restrict__ fcb)
{
    __shared__ float s_fcw[27 * 24];
    __shared__ float s_fcb[27];
    __shared__ float s_out[32 * 9 * 33];

    const int tid = threadIdx.x;
    const int b = blockIdx.y;
    const int l0 = blockIdx.x * 32;

    if (tid < 648) {
        s_fcw[tid] = fcw[tid];
    }
    if (tid < 27) {
        s_fcb[tid] = fcb[tid];
    }
    __syncthreads();

    const float* qb = g_qkv + (size_t)b * 12582912;
    float acc[27];
#pragma unroll
    for (int o = 0; o < 27; o++) {
        acc[o] = s_fcb[o];
    }

#pragma unroll 4
    for (int g = 0; g < 24; g++) {
        float v = qb[(size_t)g * 524288 + (size_t)l0 * 32 + tid];
#pragma unroll
        for (int o = 0; o < 27; o++) {
            acc[o] = fmaf(s_fcw[o * 24 + g], v, acc[o]);
        }
    }

    const int xx = tid & 31;
    const int ll = tid >> 5;
    float* fco = g_fconv + (size_t)b * 864 * LSP;
#pragma unroll
    for (int r = 0; r < 3; r++) {
#pragma unroll
        for (int oo = 0; oo < 9; oo++) {
            s_out[(xx * 9 + oo) * 33 + ll] = acc[r * 9 + oo];
        }
        __syncthreads();
#pragma unroll
        for (int it = 0; it < 9; it++) {
            int e = it * 1024 + tid;
            int l = e & 31;
            int rest = e >> 5;
            int o = rest % 9;
            int x2 = rest / 9;
            fco[(size_t)(x2 * 27 + r * 9 + o) * LSP + l0 + l] =
                s_out[(x2 * 9 + o) * 33 + l];
        }
        __syncthreads();
    }
}

// ---------------------------------------------------------------------------
// Grouped conv: 2 z-planes per block, per-thread 2oc x 8x.
// ---------------------------------------------------------------------------
#define CONV_SW_FLOATS  (27 * 4 * 10 * 36)
#define CONV_SDEP_FLOATS (8 * 729)
#define CONV_SMEM_BYTES ((CONV_SW_FLOATS + CONV_SDEP_FLOATS) * 4)

__global__ __launch_bounds__(256) void conv_kernel(
    const float* __restrict__ dep_w, const float* __restrict__ dep_b,
    const float* __restrict__ beta_p, float* __restrict__ out)
{
    extern __shared__ float sm[];
    float* sw = sm;
    float* sdep = sm + CONV_SW_FLOATS;

    const int tid = threadIdx.x;
    const int y0 = blockIdx.x * 8;
    const int z0 = blockIdx.y * 2;
    const int bg = blockIdx.z;
    const int b = bg >> 5;
    const int g = bg & 31;

    for (int e = tid; e < 8 * 729; e += 256) {
        sdep[e] = dep_w[(size_t)(g * 8) * 729 + e];
    }

    const float* fin = g_fconv + ((size_t)(b * 864 + g * 27)) * LSP;
    for (int e = tid; e < 27 * 4 * 10 * 34; e += 256) {
        int x = e % 34;
        int t1 = e / 34;
        int yy = t1 % 10;
        int t2 = t1 / 10;
        int wz = t2 & 3;
        int k = t2 >> 2;
        int gx = x - 1;
        int gy = y0 + yy - 1;
        int gz = z0 + wz - 1;
        float v = 0.0f;
        if (gx >= 0 && gx < 32 && gy >= 0 && gy < 32 && gz >= 0 && gz < 16) {
            v = fin[(size_t)k * LSP + gz * 1024 + gy * 32 + gx];
        }
        sw[((k * 4 + wz) * 10 + yy) * 36 + x] = v;
    }
    __syncthreads();

    const int xq = tid & 3;
    const int ocp = (tid >> 2) & 3;
    const int yy = (tid >> 4) & 7;
    const int zz = tid >> 7;
    const int oc0 = ocp * 2;

    float acc0[8] = {0.0f, 0.0f, 0.0f, 0.0f, 0.0f, 0.0f, 0.0f, 0.0f};
    float acc1[8] = {0.0f, 0.0f, 0.0f, 0.0f, 0.0f, 0.0f, 0.0f, 0.0f};

#pragma unroll 1
    for (int k = 0; k < 27; k++) {
#pragma unroll
        for (int dz = 0; dz < 3; dz++) {
#pragma unroll
            for (int dy = 0; dy < 3; dy++) {
                const float* wrow = &sw[((k * 4 + zz + dz) * 10 + yy + dy) * 36 + xq * 8];
                float4 wa = *reinterpret_cast<const float4*>(wrow);
                float4 wb = *reinterpret_cast<const float4*>(wrow + 4);
                float2 wc = *reinterpret_cast<const float2*>(wrow + 8);
                float win[10];
                win[0] = wa.x; win[1] = wa.y; win[2] = wa.z; win[3] = wa.w;
                win[4] = wb.x; win[5] = wb.y; win[6] = wb.z; win[7] = wb.w;
                win[8] = wc.x; win[9] = wc.y;
                const float* d0 = &sdep[oc0 * 729 + k * 27 + dz * 9 + dy * 3];
                const float* d1 = d0 + 729;
#pragma unroll
                for (int dx = 0; dx < 3; dx++) {
                    float w0 = d0[dx];
                    float w1 = d1[dx];
#pragma unroll
                    for (int c = 0; c < 8; c++) {
                        acc0[c] = fmaf(win[c + dx], w0, acc0[c]);
                        acc1[c] = fmaf(win[c + dx], w1, acc1[c]);
                    }
                }
            }
        }
    }

    const float beta = beta_p[0];
    const int ocg0 = g * 8 + oc0;
    const float b0 = dep_b[ocg0];
    const float b1 = dep_b[ocg0 + 1];
    const size_t spatbase = (size_t)b * LSP + (z0 + zz) * 1024 + (y0 + yy) * 32 + xq * 8;
#pragma unroll
    for (int c = 0; c < 8; c++) {
        float2 v;
        v.x = beta * (acc0[c] + b0);
        v.y = beta * (acc1[c] + b1);
        *reinterpret_cast<float2*>(out + (spatbase + c) * 256 + ocg0) = v;
    }
}

// ---------------------------------------------------------------------------
// Windowed attention -> bf16 split output (g_ah/g_al).
// ---------------------------------------------------------------------------
__global__ __launch_bounds__(256) void attn_kernel(const float* __restrict__ rpb)
{
    __shared__ __align__(16) float sq[64][36];
    __shared__ __align__(16) float skT[32][68];
    __shared__ __align__(16) float sv[64][36];
    __shared__ __align__(16) float sS[64][68];
    __shared__ float sbias[343];

    const int tid = threadIdx.x;
    const int win = blockIdx.x;
    const int head = blockIdx.y;
    const int b = win >> 8;
    const int rr = win & 255;
    const int dblk = rr >> 6;
    const int h2 = rr & 63;
    const int hblk = h2 >> 3;
    const int wblk = h2 & 7;

    for (int i = tid; i < 343; i += 256) {
        sbias[i] = rpb[i * 8 + head];
    }

    for (int e = tid; e < 64 * 32; e += 256) {
        int tok = e >> 5;
        int dd = e & 31;
        int z = tok >> 4;
        int y = (tok >> 2) & 3;
        int x = tok & 3;
        size_t spat = (((size_t)b * 16 + dblk * 4 + z) * 32 + hblk * 4 + y) * 32
                      + wblk * 4 + x;
        const float* src = g_qkv + spat * 768 + head * 32 + dd;
        sq[tok][dd] = src[0];
        skT[dd][tok] = src[256];
        sv[tok][dd] = src[512];
    }
    __syncthreads();

    const int i4 = tid >> 4;
    const int jq = tid & 15;
    const int i0 = i4 * 4;
    const int j0 = jq * 4;

    float dots[4][4];
#pragma unroll
    for (int r = 0; r < 4; r++) {
#pragma unroll
        for (int c = 0; c < 4; c++) {
            dots[r][c] = 0.0f;
        }
    }

#pragma unroll
    for (int d8 = 0; d8 < 4; d8++) {
        float qreg[4][8];
#pragma unroll
        for (int r = 0; r < 4; r++) {
            float4 q0 = *reinterpret_cast<const float4*>(&sq[i0 + r][d8 * 8]);
            float4 q1 = *reinterpret_cast<const float4*>(&sq[i0 + r][d8 * 8 + 4]);
            qreg[r][0] = q0.x; qreg[r][1] = q0.y; qreg[r][2] = q0.z; qreg[r][3] = q0.w;
            qreg[r][4] = q1.x; qreg[r][5] = q1.y; qreg[r][6] = q1.z; qreg[r][7] = q1.w;
        }
#pragma unroll
        for (int dd = 0; dd < 8; dd++) {
            float4 kv = *reinterpret_cast<const float4*>(&skT[d8 * 8 + dd][j0]);
#pragma unroll
            for (int r = 0; r < 4; r++) {
                dots[r][0] = fmaf(qreg[r][dd], kv.x, dots[r][0]);
                dots[r][1] = fmaf(qreg[r][dd], kv.y, dots[r][1]);
                dots[r][2] = fmaf(qreg[r][dd], kv.z, dots[r][2]);
                dots[r][3] = fmaf(qreg[r][dd], kv.w, dots[r][3]);
            }
        }
    }

    const float scale = 0.17677669529663687f;
#pragma unroll
    for (int r = 0; r < 4; r++) {
        int ti = i0 + r;
        int zi = ti >> 4;
        int yi = (ti >> 2) & 3;
        int xi = ti & 3;
        float sv4[4];
#pragma unroll
        for (int c = 0; c < 4; c++) {
            int tj = j0 + c;
            int zj = tj >> 4;
            int yj = (tj >> 2) & 3;
            int xj = tj & 3;
            int rel = (zi - zj + 3) * 49 + (yi - yj + 3) * 7 + (xi - xj + 3);
            sv4[c] = dots[r][c] * scale + sbias[rel];
        }
        float rmax = fmaxf(fmaxf(sv4[0], sv4[1]), fmaxf(sv4[2], sv4[3]));
        rmax = warp16_max(rmax);
        float rsum = 0.0f;
#pragma unroll
        for (int c = 0; c < 4; c++) {
            sv4[c] = __expf(sv4[c] - rmax);
            rsum += sv4[c];
        }
        rsum = warp16_sum(rsum);
        float inv = 1.0f / rsum;
        float4 pv;
        pv.x = sv4[0] * inv;
        pv.y = sv4[1] * inv;
        pv.z = sv4[2] * inv;
        pv.w = sv4[3] * inv;
        *reinterpret_cast<float4*>(&sS[i0 + r][j0]) = pv;
    }
    __syncthreads();

    const int p2 = tid >> 3;
    const int dg = tid & 7;
    const int r0 = p2 * 2;
    const int r1 = r0 + 1;
    float o0[4] = {0.0f, 0.0f, 0.0f, 0.0f};
    float o1[4] = {0.0f, 0.0f, 0.0f, 0.0f};
#pragma unroll 4
    for (int j = 0; j < 64; j++) {
        float4 v = *reinterpret_cast<const float4*>(&sv[j][dg * 4]);
        float pa = sS[r0][j];
        float pbv = sS[r1][j];
        o0[0] = fmaf(pa, v.x, o0[0]);
        o0[1] = fmaf(pa, v.y, o0[1]);
        o0[2] = fmaf(pa, v.z, o0[2]);
        o0[3] = fmaf(pa, v.w, o0[3]);
        o1[0] = fmaf(pbv, v.x, o1[0]);
        o1[1] = fmaf(pbv, v.y, o1[1]);
        o1[2] = fmaf(pbv, v.z, o1[2]);
        o1[3] = fmaf(pbv, v.w, o1[3]);
    }
    size_t off0 = ((size_t)win * 64 + r0) * 256 + head * 32 + dg * 4;
    size_t off1 = ((size_t)win * 64 + r1) * 256 + head * 32 + dg * 4;
#pragma unroll
    for (int pass = 0; pass < 2; pass++) {
        const float* ov = (pass == 0) ? o0 : o1;
        size_t off = (pass == 0) ? off0 : off1;
        __nv_bfloat16 hh[4];
        __nv_bfloat16 ll[4];
#pragma unroll
        for (int c = 0; c < 4; c++) {
            hh[c] = __float2bfloat16(ov[c]);
            ll[c] = __float2bfloat16(ov[c] - __bfloat162float(hh[c]));
        }
        __nv_bfloat162* hp = reinterpret_cast<__nv_bfloat162*>(g_ah + off);
        __nv_bfloat162* lp = reinterpret_cast<__nv_bfloat162*>(g_al + off);
        hp[0] = __halves2bfloat162(hh[0], hh[1]);
        hp[1] = __halves2bfloat162(hh[2], hh[3]);
        lp[0] = __halves2bfloat162(ll[0], ll[1]);
        lp[1] = __halves2bfloat162(ll[2], ll[3]);
    }
}

// ---------------------------------------------------------------------------
// Launch
// ---------------------------------------------------------------------------
extern "C" void kernel_launch(void* const* d_in, const int* in_sizes, int n_in,
                              void* d_out, int out_size)
{
    (void)in_sizes;
    (void)n_in;
    (void)out_size;
    const float* x_in   = (const float*)d_in[0];
    const float* qkv_w  = (const float*)d_in[1];
    const float* proj_w = (const float*)d_in[2];
    const float* proj_b = (const float*)d_in[3];
    const float* rpb    = (const float*)d_in[4];
    const float* fc_w   = (const float*)d_in[5];
    const float* fc_b   = (const float*)d_in[6];
    const float* dep_w  = (const float*)d_in[7];
    const float* dep_b  = (const float*)d_in[8];
    const float* alpha  = (const float*)d_in[9];
    const float* beta   = (const float*)d_in[10];
    float* out = (float*)d_out;

    float* p_qkv;
    __nv_bfloat16* p_xh;
    __nv_bfloat16* p_xl;
    __nv_bfloat16* p_ah;
    __nv_bfloat16* p_al;
    __nv_bfloat16* p_wqh;
    __nv_bfloat16* p_wql;
    __nv_bfloat16* p_pwh;
    __nv_bfloat16* p_pwl;
    cudaGetSymbolAddress((void**)&p_qkv, g_qkv);
    cudaGetSymbolAddress((void**)&p_xh, g_xh);
    cudaGetSymbolAddress((void**)&p_xl, g_xl);
    cudaGetSymbolAddress((void**)&p_ah, g_ah);
    cudaGetSymbolAddress((void**)&p_al, g_al);
    cudaGetSymbolAddress((void**)&p_wqh, g_wqh);
    cudaGetSymbolAddress((void**)&p_wql, g_wql);
    cudaGetSymbolAddress((void**)&p_pwh, g_pwh);
    cudaGetSymbolAddress((void**)&p_pwl, g_pwl);

    // bf16 splits
    split_kernel<<<16384, 256>>>(x_in, p_xh, p_xl, 4194304);
    split_kernel<<<192, 256>>>(qkv_w, p_wqh, p_wql, 49152);
    split_kernel<<<64, 256>>>(proj_w, p_pwh, p_pwl, 16384);

    // 1) qkv = x_in @ qkv_w
    gemm_bf16<0><<<dim3(6, 512), 256>>>(p_xh, p_xl, p_wqh, p_wql, p_qkv,
                                        65536, 768, 256, (const float*)0, (const float*)0);
    // 2) f_conv
    fconv_kernel<<<dim3(512, 4), 1024>>>(fc_w, fc_b);
    // 3) grouped conv -> out = beta*(conv + dep_b)
    cudaFuncSetAttribute(conv_kernel, cudaFuncAttributeMaxDynamicSharedMemorySize,
                         CONV_SMEM_BYTES);
    conv_kernel<<<dim3(4, 8, 128), 256, CONV_SMEM_BYTES>>>(dep_w, dep_b, beta, out);
    // 4) attention -> g_ah/g_al (bf16 split)
    attn_kernel<<<dim3(1024, 8), 256>>>(rpb);
    // 5) proj + window-reverse + out += alpha*(...)
    gemm_bf16<1><<<dim3(2, 512), 256>>>(p_ah, p_al, p_pwh, p_pwl, out,
                                        65536, 256, 256, proj_b, alpha);
}

// round 6
// speedup vs baseline: 1.8793x; 1.1291x over previous
#include <cuda_runtime.h>
#include <cuda_bf16.h>
#include <stdint.h>
#include <math.h>

typedef unsigned int u32;

// ---------------------------------------------------------------------------
// x_in [4,16,32,32,256], qkv_w [256,768], proj_w [256,256], proj_b [256]
// rpb_table [343,8], fc_w [27,24], fc_b [27], dep_w [256,27,3,3,3],
// dep_b [256], alpha, beta; out [4,16,32,32,256] float32
// ---------------------------------------------------------------------------
#define LSP 16384

__device__ float g_qkv  [(size_t)65536 * 768];
__device__ float g_fconv[(size_t)4 * 864 * LSP];

__device__ __nv_bfloat16 g_xh[(size_t)65536 * 256];
__device__ __nv_bfloat16 g_xl[(size_t)65536 * 256];
__device__ __nv_bfloat16 g_ah[(size_t)65536 * 256];
__device__ __nv_bfloat16 g_al[(size_t)65536 * 256];
__device__ __nv_bfloat16 g_wqh[256 * 768];
__device__ __nv_bfloat16 g_wql[256 * 768];
__device__ __nv_bfloat16 g_pwh[256 * 256];
__device__ __nv_bfloat16 g_pwl[256 * 256];

__device__ __forceinline__ u32 smem_u32(const void* p) {
    return (u32)__cvta_generic_to_shared(p);
}

__device__ __forceinline__ void ldsm_x4(u32& r0, u32& r1, u32& r2, u32& r3, u32 a) {
    asm volatile("ldmatrix.sync.aligned.m8n8.x4.shared.b16 {%0,%1,%2,%3}, [%4];\n"
                 : "=r"(r0), "=r"(r1), "=r"(r2), "=r"(r3) : "r"(a));
}

__device__ __forceinline__ void ldsm_x4t(u32& r0, u32& r1, u32& r2, u32& r3, u32 a) {
    asm volatile("ldmatrix.sync.aligned.m8n8.x4.trans.shared.b16 {%0,%1,%2,%3}, [%4];\n"
                 : "=r"(r0), "=r"(r1), "=r"(r2), "=r"(r3) : "r"(a));
}

__device__ __forceinline__ void mma_bf16(float* c, const u32* a, const u32* b) {
    asm volatile(
        "mma.sync.aligned.m16n8k16.row.col.f32.bf16.bf16.f32 "
        "{%0,%1,%2,%3}, {%4,%5,%6,%7}, {%8,%9}, {%0,%1,%2,%3};\n"
        : "+f"(c[0]), "+f"(c[1]), "+f"(c[2]), "+f"(c[3])
        : "r"(a[0]), "r"(a[1]), "r"(a[2]), "r"(a[3]), "r"(b[0]), "r"(b[1]));
}

__device__ __forceinline__ float warp16_max(float v) {
    v = fmaxf(v, __shfl_xor_sync(0xffffffffu, v, 1));
    v = fmaxf(v, __shfl_xor_sync(0xffffffffu, v, 2));
    v = fmaxf(v, __shfl_xor_sync(0xffffffffu, v, 4));
    v = fmaxf(v, __shfl_xor_sync(0xffffffffu, v, 8));
    return v;
}

__device__ __forceinline__ float warp16_sum(float v) {
    v += __shfl_xor_sync(0xffffffffu, v, 1);
    v += __shfl_xor_sync(0xffffffffu, v, 2);
    v += __shfl_xor_sync(0xffffffffu, v, 4);
    v += __shfl_xor_sync(0xffffffffu, v, 8);
    return v;
}

// ---------------------------------------------------------------------------
// Elementwise fp32 -> (bf16 hi, bf16 lo) split.
// ---------------------------------------------------------------------------
__global__ __launch_bounds__(256) void split_kernel(
    const float* __restrict__ s, __nv_bfloat16* __restrict__ h,
    __nv_bfloat16* __restrict__ l, int n4)
{
    int i = blockIdx.x * blockDim.x + threadIdx.x;
    if (i >= n4) {
        return;
    }
    float4 v = reinterpret_cast<const float4*>(s)[i];
    __nv_bfloat16 h0 = __float2bfloat16(v.x);
    __nv_bfloat16 h1 = __float2bfloat16(v.y);
    __nv_bfloat16 h2 = __float2bfloat16(v.z);
    __nv_bfloat16 h3 = __float2bfloat16(v.w);
    __nv_bfloat16 l0 = __float2bfloat16(v.x - __bfloat162float(h0));
    __nv_bfloat16 l1 = __float2bfloat16(v.y - __bfloat162float(h1));
    __nv_bfloat16 l2 = __float2bfloat16(v.z - __bfloat162float(h2));
    __nv_bfloat16 l3 = __float2bfloat16(v.w - __bfloat162float(h3));
    __nv_bfloat162* hp = reinterpret_cast<__nv_bfloat162*>(h) + i * 2;
    __nv_bfloat162* lp = reinterpret_cast<__nv_bfloat162*>(l) + i * 2;
    hp[0] = __halves2bfloat162(h0, h1);
    hp[1] = __halves2bfloat162(h2, h3);
    lp[0] = __halves2bfloat162(l0, l1);
    lp[1] = __halves2bfloat162(l2, l3);
}

// ---------------------------------------------------------------------------
// Tensor-core GEMM on pre-split bf16, double-buffered smem (dynamic, 76KB).
// C = Ah@Bh + Ah@Bl + Al@Bh. 128x128x32 tile, 256 threads.
// MODE 0: plain fp32 store. MODE 1: window-reverse + out += alpha*(acc+bias).
// smem element layout (bf16 units):
//   Ah: [2][128*40] at 0,  Al at 10240, Bh: [2][32*136] at 20480, Bl at 29184
// ---------------------------------------------------------------------------
#define GEMM_SMEM_BYTES ((2 * 5120 + 2 * 5120 + 2 * 4352 + 2 * 4352) * 2)

template<int MODE>
__global__ __launch_bounds__(256) void gemm_bf16(
    const __nv_bfloat16* __restrict__ Ah, const __nv_bfloat16* __restrict__ Al,
    const __nv_bfloat16* __restrict__ Bh, const __nv_bfloat16* __restrict__ Bl,
    float* __restrict__ C, int M, int N, int K,
    const float* __restrict__ bias, const float* __restrict__ alpha_p)
{
    extern __shared__ __nv_bfloat16 gsm[];
    __nv_bfloat16* pAh = gsm;
    __nv_bfloat16* pAl = gsm + 10240;
    __nv_bfloat16* pBh = gsm + 20480;
    __nv_bfloat16* pBl = gsm + 29184;

    const int tid = threadIdx.x;
    const int lane = tid & 31;
    const int wid = tid >> 5;
    const int wm = (wid & 1) * 64;
    const int wn = (wid >> 1) * 32;
    const int bm = blockIdx.y * 128;
    const int bn = blockIdx.x * 128;

    float acc[4][4][4];
#pragma unroll
    for (int i = 0; i < 4; i++) {
#pragma unroll
        for (int j = 0; j < 4; j++) {
#pragma unroll
            for (int r = 0; r < 4; r++) {
                acc[i][j][r] = 0.0f;
            }
        }
    }

    const int nk = K >> 5;
    uint4 rAh[2];
    uint4 rAl[2];
    uint4 rBh[2];
    uint4 rBl[2];

    // prologue: load tile 0 into regs
#pragma unroll
    for (int i = 0; i < 2; i++) {
        int u = tid + i * 256;
        int ar = u >> 2;
        int ac = (u & 3) * 8;
        size_t aidx = (size_t)(bm + ar) * K + ac;
        rAh[i] = *reinterpret_cast<const uint4*>(Ah + aidx);
        rAl[i] = *reinterpret_cast<const uint4*>(Al + aidx);
        int br = u >> 4;
        int bc = (u & 15) * 8;
        size_t bidx = (size_t)br * N + bn + bc;
        rBh[i] = *reinterpret_cast<const uint4*>(Bh + bidx);
        rBl[i] = *reinterpret_cast<const uint4*>(Bl + bidx);
    }
    // store tile 0 into stage 0
#pragma unroll
    for (int i = 0; i < 2; i++) {
        int u = tid + i * 256;
        int ar = u >> 2;
        int ac = (u & 3) * 8;
        *reinterpret_cast<uint4*>(pAh + ar * 40 + ac) = rAh[i];
        *reinterpret_cast<uint4*>(pAl + ar * 40 + ac) = rAl[i];
        int br = u >> 4;
        int bc = (u & 15) * 8;
        *reinterpret_cast<uint4*>(pBh + br * 136 + bc) = rBh[i];
        *reinterpret_cast<uint4*>(pBl + br * 136 + bc) = rBl[i];
    }
    __syncthreads();

    const int a_r = lane & 15;
    const int a_k = (lane >> 4) * 8;

    for (int kt = 0; kt < nk; kt++) {
        const int curA = (kt & 1) * 5120;
        const int curB = (kt & 1) * 4352;

        if (kt + 1 < nk) {
#pragma unroll
            for (int i = 0; i < 2; i++) {
                int u = tid + i * 256;
                int ar = u >> 2;
                int ac = (u & 3) * 8;
                size_t aidx = (size_t)(bm + ar) * K + (kt + 1) * 32 + ac;
                rAh[i] = *reinterpret_cast<const uint4*>(Ah + aidx);
                rAl[i] = *reinterpret_cast<const uint4*>(Al + aidx);
                int br = u >> 4;
                int bc = (u & 15) * 8;
                size_t bidx = (size_t)((kt + 1) * 32 + br) * N + bn + bc;
                rBh[i] = *reinterpret_cast<const uint4*>(Bh + bidx);
                rBl[i] = *reinterpret_cast<const uint4*>(Bl + bidx);
            }
        }

#pragma unroll
        for (int ks = 0; ks < 2; ks++) {
            u32 aH[4][4];
            u32 aL[4][4];
            u32 bH[4][2];
            u32 bL[4][2];
#pragma unroll
            for (int mi = 0; mi < 4; mi++) {
                u32 adr = smem_u32(pAh + curA + (wm + mi * 16 + a_r) * 40 + ks * 16 + a_k);
                ldsm_x4(aH[mi][0], aH[mi][1], aH[mi][2], aH[mi][3], adr);
                adr = smem_u32(pAl + curA + (wm + mi * 16 + a_r) * 40 + ks * 16 + a_k);
                ldsm_x4(aL[mi][0], aL[mi][1], aL[mi][2], aL[mi][3], adr);
            }
#pragma unroll
            for (int nj = 0; nj < 2; nj++) {
                u32 r0;
                u32 r1;
                u32 r2;
                u32 r3;
                u32 adr = smem_u32(pBh + curB + (ks * 16 + a_r) * 136 + wn + nj * 16 + a_k);
                ldsm_x4t(r0, r1, r2, r3, adr);
                bH[nj * 2][0] = r0;
                bH[nj * 2][1] = r1;
                bH[nj * 2 + 1][0] = r2;
                bH[nj * 2 + 1][1] = r3;
                adr = smem_u32(pBl + curB + (ks * 16 + a_r) * 136 + wn + nj * 16 + a_k);
                ldsm_x4t(r0, r1, r2, r3, adr);
                bL[nj * 2][0] = r0;
                bL[nj * 2][1] = r1;
                bL[nj * 2 + 1][0] = r2;
                bL[nj * 2 + 1][1] = r3;
            }
#pragma unroll
            for (int mi = 0; mi < 4; mi++) {
#pragma unroll
                for (int ni = 0; ni < 4; ni++) {
                    mma_bf16(acc[mi][ni], aH[mi], bH[ni]);
                    mma_bf16(acc[mi][ni], aH[mi], bL[ni]);
                    mma_bf16(acc[mi][ni], aL[mi], bH[ni]);
                }
            }
        }

        if (kt + 1 < nk) {
            const int nxtA = ((kt + 1) & 1) * 5120;
            const int nxtB = ((kt + 1) & 1) * 4352;
#pragma unroll
            for (int i = 0; i < 2; i++) {
                int u = tid + i * 256;
                int ar = u >> 2;
                int ac = (u & 3) * 8;
                *reinterpret_cast<uint4*>(pAh + nxtA + ar * 40 + ac) = rAh[i];
                *reinterpret_cast<uint4*>(pAl + nxtA + ar * 40 + ac) = rAl[i];
                int br = u >> 4;
                int bc = (u & 15) * 8;
                *reinterpret_cast<uint4*>(pBh + nxtB + br * 136 + bc) = rBh[i];
                *reinterpret_cast<uint4*>(pBl + nxtB + br * 136 + bc) = rBl[i];
            }
        }
        __syncthreads();
    }

    const int g = lane >> 2;
    const int tg = lane & 3;

    if (MODE == 0) {
#pragma unroll
        for (int mi = 0; mi < 4; mi++) {
            int row0 = bm + wm + mi * 16 + g;
#pragma unroll
            for (int ni = 0; ni < 4; ni++) {
                int col = bn + wn + ni * 8 + tg * 2;
                float2 v0;
                float2 v1;
                v0.x = acc[mi][ni][0];
                v0.y = acc[mi][ni][1];
                v1.x = acc[mi][ni][2];
                v1.y = acc[mi][ni][3];
                *reinterpret_cast<float2*>(&C[(size_t)row0 * N + col]) = v0;
                *reinterpret_cast<float2*>(&C[(size_t)(row0 + 8) * N + col]) = v1;
            }
        }
    } else {
        const float alpha = alpha_p[0];
#pragma unroll
        for (int mi = 0; mi < 4; mi++) {
#pragma unroll
            for (int half = 0; half < 2; half++) {
                int row = bm + wm + mi * 16 + g + half * 8;
                int win = row >> 6;
                int tok = row & 63;
                int b = win >> 8;
                int r2 = win & 255;
                int dblk = r2 >> 6;
                int h2 = r2 & 63;
                int hblk = h2 >> 3;
                int wblk = h2 & 7;
                int z4 = tok >> 4;
                int y4 = (tok >> 2) & 3;
                int x4 = tok & 3;
                size_t spat = (((size_t)b * 16 + dblk * 4 + z4) * 32 + hblk * 4 + y4) * 32
                              + wblk * 4 + x4;
#pragma unroll
                for (int ni = 0; ni < 4; ni++) {
                    int col = bn + wn + ni * 8 + tg * 2;
                    float2 pb = *reinterpret_cast<const float2*>(&bias[col]);
                    float* dst = &C[spat * 256 + col];
                    float2 e = *reinterpret_cast<float2*>(dst);
                    e.x += alpha * (acc[mi][ni][half * 2 + 0] + pb.x);
                    e.y += alpha * (acc[mi][ni][half * 2 + 1] + pb.y);
                    *reinterpret_cast<float2*>(dst) = e;
                }
            }
        }
    }
}

// ---------------------------------------------------------------------------
// fconv
// ---------------------------------------------------------------------------
__global__ __launch_bounds__(1024) void fconv_kernel(
    const float* __restrict__ fcw, const float* __restrict__ fcb)
{
    __shared__ float s_fcw[27 * 24];
    __shared__ float s_fcb[27];
    __shared__ float s_out[32 * 9 * 33];

    const int tid = threadIdx.x;
    const int b = blockIdx.y;
    const int l0 = blockIdx.x * 32;

    if (tid < 648) {
        s_fcw[tid] = fcw[tid];
    }
    if (tid < 27) {
        s_fcb[tid] = fcb[tid];
    }
    __syncthreads();

    const float* qb = g_qkv + (size_t)b * 12582912;
    float acc[27];
#pragma unroll
    for (int o = 0; o < 27; o++) {
        acc[o] = s_fcb[o];
    }

#pragma unroll 4
    for (int g = 0; g < 24; g++) {
        float v = qb[(size_t)g * 524288 + (size_t)l0 * 32 + tid];
#pragma unroll
        for (int o = 0; o < 27; o++) {
            acc[o] = fmaf(s_fcw[o * 24 + g], v, acc[o]);
        }
    }

    const int xx = tid & 31;
    const int ll = tid >> 5;
    float* fco = g_fconv + (size_t)b * 864 * LSP;
#pragma unroll
    for (int r = 0; r < 3; r++) {
#pragma unroll
        for (int oo = 0; oo < 9; oo++) {
            s_out[(xx * 9 + oo) * 33 + ll] = acc[r * 9 + oo];
        }
        __syncthreads();
#pragma unroll
        for (int it = 0; it < 9; it++) {
            int e = it * 1024 + tid;
            int l = e & 31;
            int rest = e >> 5;
            int o = rest % 9;
            int x2 = rest / 9;
            fco[(size_t)(x2 * 27 + r * 9 + o) * LSP + l0 + l] =
                s_out[(x2 * 9 + o) * 33 + l];
        }
        __syncthreads();
    }
}

// ---------------------------------------------------------------------------
// Grouped conv: same 2z x 8y x 32x block tile as R5 but 512 threads
// (per-thread 2oc x 4x) -> 16 warps/SM to hide LDS latency.
// ---------------------------------------------------------------------------
#define CONV_SW_FLOATS  (27 * 4 * 10 * 36)
#define CONV_SDEP_FLOATS (8 * 729)
#define CONV_SMEM_BYTES ((CONV_SW_FLOATS + CONV_SDEP_FLOATS) * 4)

__global__ __launch_bounds__(512) void conv_kernel(
    const float* __restrict__ dep_w, const float* __restrict__ dep_b,
    const float* __restrict__ beta_p, float* __restrict__ out)
{
    extern __shared__ float sm[];
    float* sw = sm;
    float* sdep = sm + CONV_SW_FLOATS;

    const int tid = threadIdx.x;
    const int y0 = blockIdx.x * 8;
    const int z0 = blockIdx.y * 2;
    const int bg = blockIdx.z;
    const int b = bg >> 5;
    const int g = bg & 31;

    for (int e = tid; e < 8 * 729; e += 512) {
        sdep[e] = dep_w[(size_t)(g * 8) * 729 + e];
    }

    const float* fin = g_fconv + ((size_t)(b * 864 + g * 27)) * LSP;
    for (int e = tid; e < 27 * 4 * 10 * 34; e += 512) {
        int x = e % 34;
        int t1 = e / 34;
        int yy = t1 % 10;
        int t2 = t1 / 10;
        int wz = t2 & 3;
        int k = t2 >> 2;
        int gx = x - 1;
        int gy = y0 + yy - 1;
        int gz = z0 + wz - 1;
        float v = 0.0f;
        if (gx >= 0 && gx < 32 && gy >= 0 && gy < 32 && gz >= 0 && gz < 16) {
            v = fin[(size_t)k * LSP + gz * 1024 + gy * 32 + gx];
        }
        sw[((k * 4 + wz) * 10 + yy) * 36 + x] = v;
    }
    __syncthreads();

    const int xq = tid & 7;
    const int ocp = (tid >> 3) & 3;
    const int yy = (tid >> 5) & 7;
    const int zz = tid >> 8;
    const int oc0 = ocp * 2;

    float acc0[4] = {0.0f, 0.0f, 0.0f, 0.0f};
    float acc1[4] = {0.0f, 0.0f, 0.0f, 0.0f};

#pragma unroll 1
    for (int k = 0; k < 27; k++) {
#pragma unroll
        for (int dz = 0; dz < 3; dz++) {
#pragma unroll
            for (int dy = 0; dy < 3; dy++) {
                const float* wrow = &sw[((k * 4 + zz + dz) * 10 + yy + dy) * 36 + xq * 4];
                float4 wa = *reinterpret_cast<const float4*>(wrow);
                float2 wb = *reinterpret_cast<const float2*>(wrow + 4);
                float win[6];
                win[0] = wa.x; win[1] = wa.y; win[2] = wa.z; win[3] = wa.w;
                win[4] = wb.x; win[5] = wb.y;
                const float* d0 = &sdep[oc0 * 729 + k * 27 + dz * 9 + dy * 3];
                const float* d1 = d0 + 729;
#pragma unroll
                for (int dx = 0; dx < 3; dx++) {
                    float w0 = d0[dx];
                    float w1 = d1[dx];
#pragma unroll
                    for (int c = 0; c < 4; c++) {
                        acc0[c] = fmaf(win[c + dx], w0, acc0[c]);
                        acc1[c] = fmaf(win[c + dx], w1, acc1[c]);
                    }
                }
            }
        }
    }

    const float beta = beta_p[0];
    const int ocg0 = g * 8 + oc0;
    const float b0 = dep_b[ocg0];
    const float b1 = dep_b[ocg0 + 1];
    const size_t spatbase = (size_t)b * LSP + (z0 + zz) * 1024 + (y0 + yy) * 32 + xq * 4;
#pragma unroll
    for (int c = 0; c < 4; c++) {
        float2 v;
        v.x = beta * (acc0[c] + b0);
        v.y = beta * (acc1[c] + b1);
        *reinterpret_cast<float2*>(out + (spatbase + c) * 256 + ocg0) = v;
    }
}

// ---------------------------------------------------------------------------
// Windowed attention -> bf16 split output (g_ah/g_al).
// ---------------------------------------------------------------------------
__global__ __launch_bounds__(256) void attn_kernel(const float* __restrict__ rpb)
{
    __shared__ __align__(16) float sq[64][36];
    __shared__ __align__(16) float skT[32][68];
    __shared__ __align__(16) float sv[64][36];
    __shared__ __align__(16) float sS[64][68];
    __shared__ float sbias[343];

    const int tid = threadIdx.x;
    const int win = blockIdx.x;
    const int head = blockIdx.y;
    const int b = win >> 8;
    const int rr = win & 255;
    const int dblk = rr >> 6;
    const int h2 = rr & 63;
    const int hblk = h2 >> 3;
    const int wblk = h2 & 7;

    for (int i = tid; i < 343; i += 256) {
        sbias[i] = rpb[i * 8 + head];
    }

    for (int e = tid; e < 64 * 32; e += 256) {
        int tok = e >> 5;
        int dd = e & 31;
        int z = tok >> 4;
        int y = (tok >> 2) & 3;
        int x = tok & 3;
        size_t spat = (((size_t)b * 16 + dblk * 4 + z) * 32 + hblk * 4 + y) * 32
                      + wblk * 4 + x;
        const float* src = g_qkv + spat * 768 + head * 32 + dd;
        sq[tok][dd] = src[0];
        skT[dd][tok] = src[256];
        sv[tok][dd] = src[512];
    }
    __syncthreads();

    const int i4 = tid >> 4;
    const int jq = tid & 15;
    const int i0 = i4 * 4;
    const int j0 = jq * 4;

    float dots[4][4];
#pragma unroll
    for (int r = 0; r < 4; r++) {
#pragma unroll
        for (int c = 0; c < 4; c++) {
            dots[r][c] = 0.0f;
        }
    }

#pragma unroll
    for (int d8 = 0; d8 < 4; d8++) {
        float qreg[4][8];
#pragma unroll
        for (int r = 0; r < 4; r++) {
            float4 q0 = *reinterpret_cast<const float4*>(&sq[i0 + r][d8 * 8]);
            float4 q1 = *reinterpret_cast<const float4*>(&sq[i0 + r][d8 * 8 + 4]);
            qreg[r][0] = q0.x; qreg[r][1] = q0.y; qreg[r][2] = q0.z; qreg[r][3] = q0.w;
            qreg[r][4] = q1.x; qreg[r][5] = q1.y; qreg[r][6] = q1.z; qreg[r][7] = q1.w;
        }
#pragma unroll
        for (int dd = 0; dd < 8; dd++) {
            float4 kv = *reinterpret_cast<const float4*>(&skT[d8 * 8 + dd][j0]);
#pragma unroll
            for (int r = 0; r < 4; r++) {
                dots[r][0] = fmaf(qreg[r][dd], kv.x, dots[r][0]);
                dots[r][1] = fmaf(qreg[r][dd], kv.y, dots[r][1]);
                dots[r][2] = fmaf(qreg[r][dd], kv.z, dots[r][2]);
                dots[r][3] = fmaf(qreg[r][dd], kv.w, dots[r][3]);
            }
        }
    }

    const float scale = 0.17677669529663687f;
#pragma unroll
    for (int r = 0; r < 4; r++) {
        int ti = i0 + r;
        int zi = ti >> 4;
        int yi = (ti >> 2) & 3;
        int xi = ti & 3;
        float sv4[4];
#pragma unroll
        for (int c = 0; c < 4; c++) {
            int tj = j0 + c;
            int zj = tj >> 4;
            int yj = (tj >> 2) & 3;
            int xj = tj & 3;
            int rel = (zi - zj + 3) * 49 + (yi - yj + 3) * 7 + (xi - xj + 3);
            sv4[c] = dots[r][c] * scale + sbias[rel];
        }
        float rmax = fmaxf(fmaxf(sv4[0], sv4[1]), fmaxf(sv4[2], sv4[3]));
        rmax = warp16_max(rmax);
        float rsum = 0.0f;
#pragma unroll
        for (int c = 0; c < 4; c++) {
            sv4[c] = __expf(sv4[c] - rmax);
            rsum += sv4[c];
        }
        rsum = warp16_sum(rsum);
        float inv = 1.0f / rsum;
        float4 pv;
        pv.x = sv4[0] * inv;
        pv.y = sv4[1] * inv;
        pv.z = sv4[2] * inv;
        pv.w = sv4[3] * inv;
        *reinterpret_cast<float4*>(&sS[i0 + r][j0]) = pv;
    }
    __syncthreads();

    const int p2 = tid >> 3;
    const int dg = tid & 7;
    const int r0 = p2 * 2;
    const int r1 = r0 + 1;
    float o0[4] = {0.0f, 0.0f, 0.0f, 0.0f};
    float o1[4] = {0.0f, 0.0f, 0.0f, 0.0f};
#pragma unroll 4
    for (int j = 0; j < 64; j++) {
        float4 v = *reinterpret_cast<const float4*>(&sv[j][dg * 4]);
        float pa = sS[r0][j];
        float pbv = sS[r1][j];
        o0[0] = fmaf(pa, v.x, o0[0]);
        o0[1] = fmaf(pa, v.y, o0[1]);
        o0[2] = fmaf(pa, v.z, o0[2]);
        o0[3] = fmaf(pa, v.w, o0[3]);
        o1[0] = fmaf(pbv, v.x, o1[0]);
        o1[1] = fmaf(pbv, v.y, o1[1]);
        o1[2] = fmaf(pbv, v.z, o1[2]);
        o1[3] = fmaf(pbv, v.w, o1[3]);
    }
    size_t off0 = ((size_t)win * 64 + r0) * 256 + head * 32 + dg * 4;
    size_t off1 = ((size_t)win * 64 + r1) * 256 + head * 32 + dg * 4;
#pragma unroll
    for (int pass = 0; pass < 2; pass++) {
        const float* ov = (pass == 0) ? o0 : o1;
        size_t off = (pass == 0) ? off0 : off1;
        __nv_bfloat16 hh[4];
        __nv_bfloat16 ll[4];
#pragma unroll
        for (int c = 0; c < 4; c++) {
            hh[c] = __float2bfloat16(ov[c]);
            ll[c] = __float2bfloat16(ov[c] - __bfloat162float(hh[c]));
        }
        __nv_bfloat162* hp = reinterpret_cast<__nv_bfloat162*>(g_ah + off);
        __nv_bfloat162* lp = reinterpret_cast<__nv_bfloat162*>(g_al + off);
        hp[0] = __halves2bfloat162(hh[0], hh[1]);
        hp[1] = __halves2bfloat162(hh[2], hh[3]);
        lp[0] = __halves2bfloat162(ll[0], ll[1]);
        lp[1] = __halves2bfloat162(ll[2], ll[3]);
    }
}

// ---------------------------------------------------------------------------
// Launch
// ---------------------------------------------------------------------------
extern "C" void kernel_launch(void* const* d_in, const int* in_sizes, int n_in,
                              void* d_out, int out_size)
{
    (void)in_sizes;
    (void)n_in;
    (void)out_size;
    const float* x_in   = (const float*)d_in[0];
    const float* qkv_w  = (const float*)d_in[1];
    const float* proj_w = (const float*)d_in[2];
    const float* proj_b = (const float*)d_in[3];
    const float* rpb    = (const float*)d_in[4];
    const float* fc_w   = (const float*)d_in[5];
    const float* fc_b   = (const float*)d_in[6];
    const float* dep_w  = (const float*)d_in[7];
    const float* dep_b  = (const float*)d_in[8];
    const float* alpha  = (const float*)d_in[9];
    const float* beta   = (const float*)d_in[10];
    float* out = (float*)d_out;

    float* p_qkv;
    __nv_bfloat16* p_xh;
    __nv_bfloat16* p_xl;
    __nv_bfloat16* p_ah;
    __nv_bfloat16* p_al;
    __nv_bfloat16* p_wqh;
    __nv_bfloat16* p_wql;
    __nv_bfloat16* p_pwh;
    __nv_bfloat16* p_pwl;
    cudaGetSymbolAddress((void**)&p_qkv, g_qkv);
    cudaGetSymbolAddress((void**)&p_xh, g_xh);
    cudaGetSymbolAddress((void**)&p_xl, g_xl);
    cudaGetSymbolAddress((void**)&p_ah, g_ah);
    cudaGetSymbolAddress((void**)&p_al, g_al);
    cudaGetSymbolAddress((void**)&p_wqh, g_wqh);
    cudaGetSymbolAddress((void**)&p_wql, g_wql);
    cudaGetSymbolAddress((void**)&p_pwh, g_pwh);
    cudaGetSymbolAddress((void**)&p_pwl, g_pwl);

    cudaFuncSetAttribute(gemm_bf16<0>, cudaFuncAttributeMaxDynamicSharedMemorySize,
                         GEMM_SMEM_BYTES);
    cudaFuncSetAttribute(gemm_bf16<1>, cudaFuncAttributeMaxDynamicSharedMemorySize,
                         GEMM_SMEM_BYTES);
    cudaFuncSetAttribute(conv_kernel, cudaFuncAttributeMaxDynamicSharedMemorySize,
                         CONV_SMEM_BYTES);

    // bf16 splits
    split_kernel<<<16384, 256>>>(x_in, p_xh, p_xl, 4194304);
    split_kernel<<<192, 256>>>(qkv_w, p_wqh, p_wql, 49152);
    split_kernel<<<64, 256>>>(proj_w, p_pwh, p_pwl, 16384);

    // 1) qkv = x_in @ qkv_w
    gemm_bf16<0><<<dim3(6, 512), 256, GEMM_SMEM_BYTES>>>(
        p_xh, p_xl, p_wqh, p_wql, p_qkv, 65536, 768, 256,
        (const float*)0, (const float*)0);
    // 2) f_conv
    fconv_kernel<<<dim3(512, 4), 1024>>>(fc_w, fc_b);
    // 3) grouped conv -> out = beta*(conv + dep_b)
    conv_kernel<<<dim3(4, 8, 128), 512, CONV_SMEM_BYTES>>>(dep_w, dep_b, beta, out);
    // 4) attention -> g_ah/g_al (bf16 split)
    attn_kernel<<<dim3(1024, 8), 256>>>(rpb);
    // 5) proj + window-reverse + out += alpha*(...)
    gemm_bf16<1><<<dim3(2, 512), 256, GEMM_SMEM_BYTES>>>(
        p_ah, p_al, p_pwh, p_pwl, out, 65536, 256, 256, proj_b, alpha);
}